// round 15
// baseline (speedup 1.0000x reference)
#include <cuda_runtime.h>
#include <cuda_bf16.h>
#include <cstdint>
#include <math.h>

#define Bc  2
#define SQc 2048
#define SKc 2048
#define Dc  1024
#define Hc  16
#define DHc 64
#define NTOK (Bc*SQc)
#define ELEMS (Bc*SQc*Dc)

typedef __nv_bfloat16 bf16;

// ---------------- scratch (static device arrays; no allocation) ----------------
__device__ bf16    g_Qh[ELEMS];                // LN(Q) bf16 (Q1 projection input)
__device__ float   g_Qn[ELEMS];                // LN(Q) fp32, tf32-pre-rounded
__device__ bf16    g_Kh[ELEMS];                // LN(K), compacted per batch
__device__ bf16    g_Wqh[Dc*Dc], g_Wkh[Dc*Dc], g_Wvh[Dc*Dc];
__device__ float   g_Wot[Dc*Dc];               // Wo, tf32-pre-rounded fp32
__device__ uint8_t g_Q1f8[ELEMS], g_K1f8[ELEMS];  // Q/K projections (e4m3, x16 scale)
__device__ bf16    g_V1b[ELEMS];               // V projection (bf16)
__device__ bf16    g_O1[ELEMS];                // attention output (bf16)
__device__ float   g_O2[ELEMS];                // Q + relu(Qn @ Wo^T + bo)
__device__ int     g_pos[NTOK];
__device__ int     g_cmask[NTOK];
__device__ int     g_cnt[Bc];

// ---------------- PTX helpers ---------------------------------------------------
__device__ __forceinline__ uint32_t smem_u32(const void* p) {
    uint32_t a;
    asm("{ .reg .u64 t; cvta.to.shared.u64 t, %1; cvt.u32.u64 %0, t; }" : "=r"(a) : "l"(p));
    return a;
}
__device__ __forceinline__ void cpa16(uint32_t saddr, const void* g) {
    asm volatile("cp.async.cg.shared.global [%0], [%1], 16;" :: "r"(saddr), "l"(g) : "memory");
}
__device__ __forceinline__ void cp_commit() {
    asm volatile("cp.async.commit_group;" ::: "memory");
}
template<int N> __device__ __forceinline__ void cp_wait() {
    asm volatile("cp.async.wait_group %0;" :: "n"(N) : "memory");
}
__device__ __forceinline__ void ldm4(uint32_t* r, uint32_t a) {
    asm volatile("ldmatrix.sync.aligned.m8n8.x4.shared.b16 {%0,%1,%2,%3}, [%4];"
        : "=r"(r[0]), "=r"(r[1]), "=r"(r[2]), "=r"(r[3]) : "r"(a));
}
__device__ __forceinline__ void ldm4t(uint32_t* r, uint32_t a) {
    asm volatile("ldmatrix.sync.aligned.m8n8.x4.trans.shared.b16 {%0,%1,%2,%3}, [%4];"
        : "=r"(r[0]), "=r"(r[1]), "=r"(r[2]), "=r"(r[3]) : "r"(a));
}
__device__ __forceinline__ void mmabf(float* d, const uint32_t* a, const uint32_t* b) {
    asm volatile("mma.sync.aligned.m16n8k16.row.col.f32.bf16.bf16.f32 "
        "{%0,%1,%2,%3}, {%4,%5,%6,%7}, {%8,%9}, {%0,%1,%2,%3};"
        : "+f"(d[0]), "+f"(d[1]), "+f"(d[2]), "+f"(d[3])
        : "r"(a[0]), "r"(a[1]), "r"(a[2]), "r"(a[3]), "r"(b[0]), "r"(b[1]));
}
__device__ __forceinline__ void mmaf8(float* d, const uint32_t* a, const uint32_t* b) {
    asm volatile("mma.sync.aligned.m16n8k32.row.col.f32.e4m3.e4m3.f32 "
        "{%0,%1,%2,%3}, {%4,%5,%6,%7}, {%8,%9}, {%0,%1,%2,%3};"
        : "+f"(d[0]), "+f"(d[1]), "+f"(d[2]), "+f"(d[3])
        : "r"(a[0]), "r"(a[1]), "r"(a[2]), "r"(a[3]), "r"(b[0]), "r"(b[1]));
}
__device__ __forceinline__ void mmatf(float* d, const uint32_t* a, uint32_t b0, uint32_t b1) {
    asm volatile("mma.sync.aligned.m16n8k8.row.col.f32.tf32.tf32.f32 "
        "{%0,%1,%2,%3}, {%4,%5,%6,%7}, {%8,%9}, {%0,%1,%2,%3};"
        : "+f"(d[0]), "+f"(d[1]), "+f"(d[2]), "+f"(d[3])
        : "r"(a[0]), "r"(a[1]), "r"(a[2]), "r"(a[3]), "r"(b0), "r"(b1));
}
__device__ __forceinline__ float round_tf32(float f) {
    uint32_t y;
    asm("cvt.rna.tf32.f32 %0, %1;" : "=r"(y) : "f"(f));
    return __uint_as_float(y);
}
__device__ __forceinline__ uint32_t packbf2(float lo, float hi) {
    __nv_bfloat162 t = __floats2bfloat162_rn(lo, hi);
    return *(uint32_t*)&t;
}
__device__ __forceinline__ uint16_t packf8(float lo, float hi) {
    uint16_t r;
    asm("cvt.rn.satfinite.e4m3x2.f32 %0, %1, %2;" : "=h"(r) : "f"(hi), "f"(lo));
    return r;
}

// ---------------- mask prefix + compact-domain mask + pad zeroing ---------------
__global__ __launch_bounds__(1024) void prefix_kernel(const int* __restrict__ mask,
                                                      int* __restrict__ pos,
                                                      int* __restrict__ cmask,
                                                      int* __restrict__ cnt,
                                                      bf16* __restrict__ Knc) {
    int b = blockIdx.x;
    const int* m = mask + b * SKc;
    int t = threadIdx.x;
    int lane = t & 31, w = t >> 5;
    int v0 = m[2 * t], v1 = m[2 * t + 1];
    int s = v0 + v1;
    int sc = s;
    #pragma unroll
    for (int o = 1; o < 32; o <<= 1) {
        int n = __shfl_up_sync(0xffffffffu, sc, o);
        if (lane >= o) sc += n;
    }
    __shared__ int wt[32];
    if (lane == 31) wt[w] = sc;
    __syncthreads();
    if (w == 0) {
        int x = wt[lane];
        #pragma unroll
        for (int o = 1; o < 32; o <<= 1) {
            int n = __shfl_up_sync(0xffffffffu, x, o);
            if (lane >= o) x += n;
        }
        wt[lane] = x;
    }
    __syncthreads();
    int base = ((w > 0) ? wt[w - 1] : 0) + (sc - s);
    pos[b * SKc + 2 * t]     = base;
    pos[b * SKc + 2 * t + 1] = base + v0;
    int total = wt[31];
    if (t == 0) cnt[b] = total;
    cmask[b * SKc + 2 * t]     = (2 * t     < total) ? 1 : 0;
    cmask[b * SKc + 2 * t + 1] = (2 * t + 1 < total) ? 1 : 0;
    int padN = ((total + 127) >> 7) << 7;
    if (padN > SKc) padN = SKc;
    int nz = (padN - total) * (Dc / 4);
    uint2* dst = (uint2*)(Knc + ((size_t)b * SKc + total) * Dc);
    uint2 z; z.x = 0; z.y = 0;
    for (int i = t; i < nz; i += 1024) dst[i] = z;
}

// ---------------- merged LN (Q + compacted K) + weight conversion ----------------
// blocks [0,NTOK): Q LN; [NTOK,2*NTOK): K LN compact; [2*NTOK, 2*NTOK+4096): wconv
__global__ __launch_bounds__(256) void ln_wconv_kernel(const float* __restrict__ Qx,
                                                       const float* __restrict__ Kx,
                                                       const float* __restrict__ gq,
                                                       const float* __restrict__ bq,
                                                       const float* __restrict__ gk,
                                                       const float* __restrict__ bk,
                                                       const int* __restrict__ mask,
                                                       const int* __restrict__ pos,
                                                       const float* __restrict__ Wq,
                                                       const float* __restrict__ Wk,
                                                       const float* __restrict__ Wv,
                                                       const float* __restrict__ Wo,
                                                       bf16* __restrict__ Qhi,
                                                       float* __restrict__ Qf32,
                                                       bf16* __restrict__ Khi,
                                                       bf16* __restrict__ qh,
                                                       bf16* __restrict__ kh,
                                                       bf16* __restrict__ vh,
                                                       float* __restrict__ ot) {
    int blk = blockIdx.x;
    if (blk >= 2 * NTOK) {
        // ---- weight conversion part ----
        int wb = blk - 2 * NTOK;
        int m = wb >> 10;
        int i = (wb & 1023) * 256 + threadIdx.x;
        size_t base = (size_t)i * 4;
        if (m == 3) {
            float4 v = ((const float4*)Wo)[i];
            float4 r;
            r.x = round_tf32(v.x); r.y = round_tf32(v.y);
            r.z = round_tf32(v.z); r.w = round_tf32(v.w);
            *(float4*)(ot + base) = r;
            return;
        }
        const float* W = (m == 0) ? Wq : (m == 1) ? Wk : Wv;
        bf16* hi = (m == 0) ? qh : (m == 1) ? kh : vh;
        float4 v = ((const float4*)W)[i];
        __nv_bfloat162 hA = __floats2bfloat162_rn(v.x, v.y);
        __nv_bfloat162 hB = __floats2bfloat162_rn(v.z, v.w);
        *(__nv_bfloat162*)(hi + base)     = hA;
        *(__nv_bfloat162*)(hi + base + 2) = hB;
        return;
    }
    int isK = (blk >= NTOK);
    int row = isK ? (blk - NTOK) : blk;
    if (isK && !mask[row]) return;
    const float* x = isK ? Kx : Qx;
    const float* g = isK ? gk : gq;
    const float* b = isK ? bk : bq;
    int t = threadIdx.x;
    const float4* xr = (const float4*)(x + (size_t)row * Dc);
    float4 v = xr[t];
    float s  = v.x + v.y + v.z + v.w;
    float ss = v.x*v.x + v.y*v.y + v.z*v.z + v.w*v.w;
    #pragma unroll
    for (int o = 16; o > 0; o >>= 1) {
        s  += __shfl_xor_sync(0xffffffffu, s,  o);
        ss += __shfl_xor_sync(0xffffffffu, ss, o);
    }
    __shared__ float red[2][8];
    int w = t >> 5, l = t & 31;
    if (l == 0) { red[0][w] = s; red[1][w] = ss; }
    __syncthreads();
    float st = 0.f, sst = 0.f;
    #pragma unroll
    for (int i = 0; i < 8; i++) { st += red[0][i]; sst += red[1][i]; }
    float mean = st * (1.0f / Dc);
    float var  = sst * (1.0f / Dc) - mean * mean;
    float rstd = rsqrtf(var + 1e-5f);
    float4 gg = ((const float4*)g)[t];
    float4 bb = ((const float4*)b)[t];
    float4 o;
    o.x = (v.x - mean) * rstd * gg.x + bb.x;
    o.y = (v.y - mean) * rstd * gg.y + bb.y;
    o.z = (v.z - mean) * rstd * gg.z + bb.z;
    o.w = (v.w - mean) * rstd * gg.w + bb.w;
    __nv_bfloat162 hA = __floats2bfloat162_rn(o.x, o.y);
    __nv_bfloat162 hB = __floats2bfloat162_rn(o.z, o.w);
    if (!isK) {
        size_t base = (size_t)row * Dc + t * 4;
        float4 r;
        r.x = round_tf32(o.x); r.y = round_tf32(o.y);
        r.z = round_tf32(o.z); r.w = round_tf32(o.w);
        *(float4*)(Qf32 + base) = r;
        *(__nv_bfloat162*)(Qhi + base)     = hA;
        *(__nv_bfloat162*)(Qhi + base + 2) = hB;
    } else {
        int bb_ = row >> 11;
        size_t base = ((size_t)bb_ * SKc + pos[row]) * Dc + t * 4;
        *(__nv_bfloat162*)(Khi + base)     = hA;
        *(__nv_bfloat162*)(Khi + base + 2) = hB;
    }
}

// ---------------- unified GEMM (3-stage pipeline, 1 barrier/chunk) ---------------
// zbase selects slice: z = blockIdx.z + zbase.
// z=0: O2 = Q + relu(tf32 Qn@Wot^T + bo), BK=32, 32 chunks
// z=1: Q1 (bf16 -> e4m3 x16), BK=64, 16 chunks; z=2: K1 compact; z=3: V1 compact
#define STG   36864
#define GSMEM (3*STG)
__global__ __launch_bounds__(256, 2) void gemm_all_kernel(const bf16* __restrict__ Qh,
                                                          const bf16* __restrict__ Kh,
                                                          const float* __restrict__ Qn,
                                                          const float* __restrict__ Wot,
                                                          const bf16* __restrict__ Wqh,
                                                          const bf16* __restrict__ Wkh,
                                                          const bf16* __restrict__ Wvh,
                                                          const float* __restrict__ bq,
                                                          const float* __restrict__ bk,
                                                          const float* __restrict__ bv,
                                                          const float* __restrict__ bo,
                                                          const float* __restrict__ Qres,
                                                          const int* __restrict__ cnt,
                                                          uint8_t* __restrict__ Q1f8,
                                                          uint8_t* __restrict__ K1f8,
                                                          bf16* __restrict__ V1b,
                                                          float* __restrict__ O2,
                                                          int zbase) {
    int z = blockIdx.z + zbase;
    int m0 = blockIdx.y * 128, n0 = blockIdx.x * 128;
    if (z >= 2) {
        int batch = m0 >> 11;
        int ml = m0 & 2047;
        int padN = ((cnt[batch] + 127) >> 7) << 7;
        if (ml >= padN) return;
    }
    extern __shared__ char sm[];
    uint32_t sb = smem_u32(sm);
    int tid = threadIdx.x, lane = tid & 31, warp = tid >> 5;
    int wm = (warp >> 1) * 32, wn = (warp & 1) * 64;
    int cq = 2 * (lane & 3);

    float acc[2][8][4];
    #pragma unroll
    for (int mt = 0; mt < 2; mt++)
        #pragma unroll
        for (int nt = 0; nt < 8; nt++)
            #pragma unroll
            for (int j = 0; j < 4; j++) acc[mt][nt][j] = 0.f;

    if (z == 0) {
        const float* Ag = Qn  + (size_t)m0 * Dc;
        const float* Wg = Wot + (size_t)n0 * Dc;
        auto ldstage = [&](int st, int k0) {
            uint32_t s0 = sb + st * STG;
            #pragma unroll
            for (int i = 0; i < 4; i++) {
                int idx = tid + i * 256;
                int r = idx >> 3, c = idx & 7;
                uint32_t so = r * 144 + c * 16;
                size_t   go = (size_t)r * Dc + k0 + c * 4;
                cpa16(s0 +         so, Ag + go);
                cpa16(s0 + 18432 + so, Wg + go);
            }
        };
        ldstage(0, 0);  cp_commit();
        ldstage(1, 32); cp_commit();
        uint32_t aoffl = (lane & 15) * 144 + (lane >> 4) * 16;
        uint32_t boffl = ((lane & 7) + ((lane >> 4) << 3)) * 144 + ((lane >> 3) & 1) * 16;
        int st = 0, ld = 2;
        #pragma unroll 1
        for (int c = 0; c < 32; c++) {
            if (c + 1 < 32) cp_wait<1>(); else cp_wait<0>();
            __syncthreads();
            if (c + 2 < 32) { ldstage(ld, (c + 2) * 32); cp_commit(); }
            uint32_t SA = sb + st * STG;
            #pragma unroll
            for (int ks = 0; ks < 4; ks++) {
                uint32_t ar[2][4];
                #pragma unroll
                for (int mt = 0; mt < 2; mt++)
                    ldm4(ar[mt], SA + (wm + mt * 16) * 144 + aoffl + ks * 32);
                #pragma unroll
                for (int np = 0; np < 4; np++) {
                    uint32_t br[4];
                    ldm4(br, SA + 18432 + (wn + np * 16) * 144 + boffl + ks * 32);
                    #pragma unroll
                    for (int mt = 0; mt < 2; mt++) {
                        mmatf(acc[mt][2*np],   ar[mt], br[0], br[1]);
                        mmatf(acc[mt][2*np+1], ar[mt], br[2], br[3]);
                    }
                }
            }
            st = (st == 2) ? 0 : st + 1;
            ld = (ld == 2) ? 0 : ld + 1;
        }
        #pragma unroll
        for (int mt = 0; mt < 2; mt++) {
            int row0 = m0 + wm + mt * 16 + (lane >> 2);
            #pragma unroll
            for (int nt = 0; nt < 8; nt++) {
                int col = n0 + wn + nt * 8 + cq;
                float b0 = bo[col], b1 = bo[col + 1];
                float2 q0 = *(const float2*)(Qres + (size_t)row0 * Dc + col);
                float2 q1 = *(const float2*)(Qres + (size_t)(row0 + 8) * Dc + col);
                float2 v0 = make_float2(q0.x + fmaxf(acc[mt][nt][0] + b0, 0.f),
                                        q0.y + fmaxf(acc[mt][nt][1] + b1, 0.f));
                float2 v1 = make_float2(q1.x + fmaxf(acc[mt][nt][2] + b0, 0.f),
                                        q1.y + fmaxf(acc[mt][nt][3] + b1, 0.f));
                *(float2*)(O2 + (size_t)row0 * Dc + col)       = v0;
                *(float2*)(O2 + (size_t)(row0 + 8) * Dc + col) = v1;
            }
        }
        return;
    }

    const bf16* A  = (z == 1) ? Qh : Kh;
    const bf16* Wh = (z == 1) ? Wqh : (z == 2) ? Wkh : Wvh;
    const float* bias = (z == 1) ? bq : (z == 2) ? bk : bv;
    const bf16* Ahg = A  + (size_t)m0 * Dc;
    const bf16* Whg = Wh + (size_t)n0 * Dc;

    auto ldstage = [&](int st, int k0) {
        uint32_t s0 = sb + st * STG;
        #pragma unroll
        for (int i = 0; i < 4; i++) {
            int idx = tid + i * 256;
            int r = idx >> 3, c = idx & 7;
            uint32_t so = r * 144 + c * 16;
            size_t   go = (size_t)r * Dc + k0 + c * 8;
            cpa16(s0 +         so, Ahg + go);
            cpa16(s0 + 18432 + so, Whg + go);
        }
    };
    ldstage(0, 0);  cp_commit();
    ldstage(1, 64); cp_commit();

    int g8 = lane >> 3, r8 = lane & 7;
    uint32_t aoffl = (lane & 15) * 144 + (lane >> 4) * 16;
    uint32_t boffl = ((g8 >> 1) * 8 + r8) * 144 + (g8 & 1) * 16;
    int st = 0, ld = 2;

    #pragma unroll 1
    for (int c = 0; c < 16; c++) {
        if (c + 1 < 16) cp_wait<1>(); else cp_wait<0>();
        __syncthreads();
        if (c + 2 < 16) { ldstage(ld, (c + 2) * 64); cp_commit(); }
        uint32_t SA = sb + st * STG;
        #pragma unroll
        for (int ks = 0; ks < 4; ks++) {
            uint32_t ah[2][4];
            #pragma unroll
            for (int mt = 0; mt < 2; mt++)
                ldm4(ah[mt], SA + (wm + mt * 16) * 144 + aoffl + ks * 32);
            #pragma unroll
            for (int np = 0; np < 4; np++) {
                uint32_t bh[4];
                ldm4(bh, SA + 18432 + (wn + np * 16) * 144 + boffl + ks * 32);
                #pragma unroll
                for (int mt = 0; mt < 2; mt++) {
                    mmabf(acc[mt][2*np],   ah[mt], bh);
                    mmabf(acc[mt][2*np+1], ah[mt], bh + 2);
                }
            }
        }
        st = (st == 2) ? 0 : st + 1;
        ld = (ld == 2) ? 0 : ld + 1;
    }

    #pragma unroll
    for (int mt = 0; mt < 2; mt++) {
        int row0 = m0 + wm + mt * 16 + (lane >> 2);
        #pragma unroll
        for (int nt = 0; nt < 8; nt++) {
            int col = n0 + wn + nt * 8 + cq;
            float b0 = bias[col], b1 = bias[col + 1];
            float c00 = acc[mt][nt][0] + b0, c01 = acc[mt][nt][1] + b1;
            float c10 = acc[mt][nt][2] + b0, c11 = acc[mt][nt][3] + b1;
            if (z == 3) {
                *(uint32_t*)(V1b + (size_t)row0 * Dc + col)       = packbf2(c00, c01);
                *(uint32_t*)(V1b + (size_t)(row0 + 8) * Dc + col) = packbf2(c10, c11);
            } else {
                uint8_t* dst = (z == 1) ? Q1f8 : K1f8;
                *(uint16_t*)(dst + (size_t)row0 * Dc + col)       = packf8(c00 * 16.f, c01 * 16.f);
                *(uint16_t*)(dst + (size_t)(row0 + 8) * Dc + col) = packf8(c10 * 16.f, c11 * 16.f);
            }
        }
    }
}

// ---------------- flash attention: fp8 QK + bf16 PV, 3-stage --------------------
#define AQ_OFF   0
#define AK_OFF   10240
#define AV_OFF   25600
#define AM_OFF   53248
#define ASMEM    54016
__global__ __launch_bounds__(256, 2) void attn_mma_kernel(const uint8_t* __restrict__ Qf8,
                                                          const uint8_t* __restrict__ Kf8,
                                                          const bf16* __restrict__ Vb,
                                                          const int* __restrict__ cmask,
                                                          const int* __restrict__ cnt,
                                                          bf16* __restrict__ O1) {
    extern __shared__ char sm[];
    uint32_t sb = smem_u32(sm);
    int tid = threadIdx.x, lane = tid & 31, warp = tid >> 5;
    int q0 = blockIdx.x * 128;
    int h  = blockIdx.y;
    int b  = blockIdx.z;
    const uint8_t* Qg = Qf8 + ((size_t)(b * SQc + q0)) * Dc + h * DHc;
    const uint8_t* Kg = Kf8 + ((size_t)b * SKc) * Dc + h * DHc;
    const bf16*    Vg = Vb  + ((size_t)b * SKc) * Dc + h * DHc;
    const int*     mg = cmask + b * SKc;
    int nch = (cnt[b] + 63) >> 6;

    auto ldkv = [&](int st, int k0) {
        {
            int r = tid >> 2, c = tid & 3;
            cpa16(sb + AK_OFF + st * 5120 + r * 80 + c * 16,
                  Kg + (size_t)(k0 + r) * Dc + c * 16);
        }
        #pragma unroll
        for (int i = 0; i < 2; i++) {
            int idx = tid + i * 256;
            int r = idx >> 3, c = idx & 7;
            cpa16(sb + AV_OFF + st * 9216 + r * 144 + c * 16,
                  Vg + (size_t)(k0 + r) * Dc + c * 8);
        }
        if (tid < 16) cpa16(sb + AM_OFF + st * 256 + tid * 16, mg + k0 + tid * 4);
    };

    #pragma unroll
    for (int i = 0; i < 2; i++) {
        int idx = tid + i * 256;
        int r = idx >> 2, c = idx & 3;
        cpa16(sb + AQ_OFF + r * 80 + c * 16, Qg + (size_t)r * Dc + c * 16);
    }
    ldkv(0, 0);
    cp_commit();
    if (nch > 1) { ldkv(1, 64); cp_commit(); }

    int m0 = warp * 16;
    int g8 = lane >> 3, r8 = lane & 7;
    int cq = 2 * (lane & 3);
    uint32_t qaddr = sb + AQ_OFF + (m0 + (lane & 15)) * 80 + (lane >> 4) * 16;
    uint32_t klane = ((g8 >> 1) * 8 + r8) * 80 + (g8 & 1) * 16;
    uint32_t vlane = ((g8 & 1) * 8 + r8) * 144 + (g8 >> 1) * 16;
    const float SC2 = 0.03125f / 256.f;

    float o[8][4];
    #pragma unroll
    for (int dt = 0; dt < 8; dt++)
        #pragma unroll
        for (int j = 0; j < 4; j++) o[dt][j] = 0.f;
    float ls0 = 0.f, ls1 = 0.f;
    int st = 0, ld = 2;

    #pragma unroll 1
    for (int c = 0; c < nch; c++) {
        if (c + 1 < nch) cp_wait<1>(); else cp_wait<0>();
        __syncthreads();
        if (c + 2 < nch) { ldkv(ld, (c + 2) * 64); cp_commit(); }

        uint32_t Kst = sb + AK_OFF + st * 5120 + klane;
        uint32_t Vst = sb + AV_OFF + st * 9216 + vlane;
        const int* mp = (const int*)(sm + AM_OFF + st * 256);

        float s_[8][4];
        #pragma unroll
        for (int nt = 0; nt < 8; nt++)
            #pragma unroll
            for (int j = 0; j < 4; j++) s_[nt][j] = 0.f;
        #pragma unroll
        for (int ks = 0; ks < 2; ks++) {
            uint32_t aq[4];
            ldm4(aq, qaddr + ks * 32);
            #pragma unroll
            for (int np = 0; np < 4; np++) {
                uint32_t bk[4];
                ldm4(bk, Kst + np * 1280 + ks * 32);
                mmaf8(s_[2*np],   aq, bk);
                mmaf8(s_[2*np+1], aq, bk + 2);
            }
        }

        uint32_t pr0[8], pr1[8];
        #pragma unroll
        for (int nt = 0; nt < 8; nt++) {
            float f0 = (float)mp[nt * 8 + cq];
            float f1 = (float)mp[nt * 8 + cq + 1];
            float p0 = __expf(s_[nt][0] * SC2) * f0;
            float p1 = __expf(s_[nt][1] * SC2) * f1;
            float p2 = __expf(s_[nt][2] * SC2) * f0;
            float p3 = __expf(s_[nt][3] * SC2) * f1;
            ls0 += p0 + p1;
            ls1 += p2 + p3;
            pr0[nt] = packbf2(p0, p1);
            pr1[nt] = packbf2(p2, p3);
        }

        #pragma unroll
        for (int ks2 = 0; ks2 < 4; ks2++) {
            uint32_t pf[4] = { pr0[2*ks2], pr1[2*ks2], pr0[2*ks2+1], pr1[2*ks2+1] };
            #pragma unroll
            for (int dp = 0; dp < 4; dp++) {
                uint32_t bv[4];
                ldm4t(bv, Vst + ks2 * 2304 + dp * 32);
                mmabf(o[2*dp],   pf, bv);
                mmabf(o[2*dp+1], pf, bv + 2);
            }
        }
        st = (st == 2) ? 0 : st + 1;
        ld = (ld == 2) ? 0 : ld + 1;
    }

    ls0 += __shfl_xor_sync(0xffffffffu, ls0, 1);
    ls0 += __shfl_xor_sync(0xffffffffu, ls0, 2);
    ls1 += __shfl_xor_sync(0xffffffffu, ls1, 1);
    ls1 += __shfl_xor_sync(0xffffffffu, ls1, 2);
    float i0 = 1.f / ls0, i1 = 1.f / ls1;
    int row0 = q0 + m0 + (lane >> 2);
    bf16* Or0 = O1 + ((size_t)(b * SQc) + row0) * Dc + h * DHc + cq;
    bf16* Or1 = Or0 + (size_t)8 * Dc;
    #pragma unroll
    for (int dt = 0; dt < 8; dt++) {
        *(uint32_t*)(Or0 + dt * 8) = packbf2(o[dt][0] * i0, o[dt][1] * i0);
        *(uint32_t*)(Or1 + dt * 8) = packbf2(o[dt][2] * i1, o[dt][3] * i1);
    }
}

// ---------------- final LayerNorm over (bf16 O1 + O2s) --------------------------
__global__ __launch_bounds__(256) void final_ln_kernel(const bf16* __restrict__ O1,
                                                       const float* __restrict__ O2s,
                                                       const float* __restrict__ g,
                                                       const float* __restrict__ b,
                                                       float* __restrict__ out) {
    int row = blockIdx.x;
    int t = threadIdx.x;
    size_t base = (size_t)row * Dc;
    __nv_bfloat162 a0 = *(const __nv_bfloat162*)(O1 + base + t * 4);
    __nv_bfloat162 a1 = *(const __nv_bfloat162*)(O1 + base + t * 4 + 2);
    float4 o2 = ((const float4*)(O2s + base))[t];
    float4 v;
    v.x = __bfloat162float(a0.x) + o2.x;
    v.y = __bfloat162float(a0.y) + o2.y;
    v.z = __bfloat162float(a1.x) + o2.z;
    v.w = __bfloat162float(a1.y) + o2.w;
    float s  = v.x + v.y + v.z + v.w;
    float ss = v.x*v.x + v.y*v.y + v.z*v.z + v.w*v.w;
    #pragma unroll
    for (int o = 16; o > 0; o >>= 1) {
        s  += __shfl_xor_sync(0xffffffffu, s,  o);
        ss += __shfl_xor_sync(0xffffffffu, ss, o);
    }
    __shared__ float red[2][8];
    int w = t >> 5, l = t & 31;
    if (l == 0) { red[0][w] = s; red[1][w] = ss; }
    __syncthreads();
    float st = 0.f, sst = 0.f;
    #pragma unroll
    for (int i = 0; i < 8; i++) { st += red[0][i]; sst += red[1][i]; }
    float mean = st * (1.0f / Dc);
    float var  = sst * (1.0f / Dc) - mean * mean;
    float rstd = rsqrtf(var + 1e-5f);
    float4 gg = ((const float4*)g)[t];
    float4 bb = ((const float4*)b)[t];
    float4 o;
    o.x = (v.x - mean) * rstd * gg.x + bb.x;
    o.y = (v.y - mean) * rstd * gg.y + bb.y;
    o.z = (v.z - mean) * rstd * gg.z + bb.z;
    o.w = (v.w - mean) * rstd * gg.w + bb.w;
    ((float4*)(out + base))[t] = o;
}

// ---------------- launch (two-stream overlap: attention || Wo GEMM) -------------
static cudaStream_t g_s2 = nullptr;
static cudaEvent_t  g_e1 = nullptr, g_e2 = nullptr;

extern "C" void kernel_launch(void* const* d_in, const int* in_sizes, int n_in,
                              void* d_out, int out_size) {
    const float* Q       = (const float*)d_in[0];
    const float* K       = (const float*)d_in[1];
    const int*   padm    = (const int*)d_in[2];
    const float* Wq      = (const float*)d_in[3];
    const float* Wk      = (const float*)d_in[4];
    const float* Wv      = (const float*)d_in[5];
    const float* Wo      = (const float*)d_in[6];
    const float* bq      = (const float*)d_in[7];
    const float* bk      = (const float*)d_in[8];
    const float* bv      = (const float*)d_in[9];
    const float* bo      = (const float*)d_in[10];
    const float* ln_q_g  = (const float*)d_in[11];
    const float* ln_q_b  = (const float*)d_in[12];
    const float* ln_kv_g = (const float*)d_in[13];
    const float* ln_kv_b = (const float*)d_in[14];
    const float* ln_f_g  = (const float*)d_in[15];
    const float* ln_f_b  = (const float*)d_in[16];
    float* out = (float*)d_out;

    if (g_s2 == nullptr) {
        cudaStreamCreateWithFlags(&g_s2, cudaStreamNonBlocking);
        cudaEventCreateWithFlags(&g_e1, cudaEventDisableTiming);
        cudaEventCreateWithFlags(&g_e2, cudaEventDisableTiming);
    }

    bf16 *pQh, *pKh, *pWqh, *pWkh, *pWvh, *pV1b, *pO1;
    uint8_t *pQ1f8, *pK1f8;
    float *pQn, *pWot, *pO2;
    int *pPos, *pCmask, *pCnt;
    cudaGetSymbolAddress((void**)&pQh, g_Qh);
    cudaGetSymbolAddress((void**)&pQn, g_Qn);
    cudaGetSymbolAddress((void**)&pKh, g_Kh);
    cudaGetSymbolAddress((void**)&pWqh, g_Wqh);
    cudaGetSymbolAddress((void**)&pWkh, g_Wkh);
    cudaGetSymbolAddress((void**)&pWvh, g_Wvh);
    cudaGetSymbolAddress((void**)&pWot, g_Wot);
    cudaGetSymbolAddress((void**)&pQ1f8, g_Q1f8);
    cudaGetSymbolAddress((void**)&pK1f8, g_K1f8);
    cudaGetSymbolAddress((void**)&pV1b, g_V1b);
    cudaGetSymbolAddress((void**)&pO1, g_O1);
    cudaGetSymbolAddress((void**)&pO2, g_O2);
    cudaGetSymbolAddress((void**)&pPos, g_pos);
    cudaGetSymbolAddress((void**)&pCmask, g_cmask);
    cudaGetSymbolAddress((void**)&pCnt, g_cnt);

    cudaFuncSetAttribute(gemm_all_kernel, cudaFuncAttributeMaxDynamicSharedMemorySize, GSMEM);
    cudaFuncSetAttribute(attn_mma_kernel, cudaFuncAttributeMaxDynamicSharedMemorySize, ASMEM);

    prefix_kernel<<<Bc, 1024>>>(padm, pPos, pCmask, pCnt, pKh);
    ln_wconv_kernel<<<2 * NTOK + 4096, 256>>>(Q, K, ln_q_g, ln_q_b, ln_kv_g, ln_kv_b,
                                              padm, pPos, Wq, Wk, Wv, Wo,
                                              pQh, pQn, pKh, pWqh, pWkh, pWvh, pWot);

    // projections (z = 1..3)
    dim3 gproj(Dc / 128, NTOK / 128, 3);
    gemm_all_kernel<<<gproj, 256, GSMEM>>>(pQh, pKh, pQn, pWot,
                                           pWqh, pWkh, pWvh,
                                           bq, bk, bv, bo, Q, pCnt,
                                           pQ1f8, pK1f8, pV1b, pO2, 1);

    // fork: attention (stream 2) || Wo tf32 GEMM (main stream)
    cudaEventRecord(g_e1, 0);
    cudaStreamWaitEvent(g_s2, g_e1, 0);

    dim3 agrid(SQc / 128, Hc, Bc);
    attn_mma_kernel<<<agrid, 256, ASMEM, g_s2>>>(pQ1f8, pK1f8, pV1b, pCmask, pCnt, pO1);
    cudaEventRecord(g_e2, g_s2);

    dim3 gwo(Dc / 128, NTOK / 128, 1);
    gemm_all_kernel<<<gwo, 256, GSMEM>>>(pQh, pKh, pQn, pWot,
                                         pWqh, pWkh, pWvh,
                                         bq, bk, bv, bo, Q, pCnt,
                                         pQ1f8, pK1f8, pV1b, pO2, 0);

    // join, then final LN
    cudaStreamWaitEvent(0, g_e2, 0);
    final_ln_kernel<<<NTOK, 256>>>(pO1, pO2, ln_f_g, ln_f_b, out);
}

// round 16
// speedup vs baseline: 1.0951x; 1.0951x over previous
#include <cuda_runtime.h>
#include <cuda_bf16.h>
#include <cstdint>
#include <math.h>

#define Bc  2
#define SQc 2048
#define SKc 2048
#define Dc  1024
#define Hc  16
#define DHc 64
#define NTOK (Bc*SQc)
#define ELEMS (Bc*SQc*Dc)

typedef __nv_bfloat16 bf16;

// ---------------- scratch (static device arrays; no allocation) ----------------
__device__ bf16    g_Qh[ELEMS];                // LN(Q) bf16 (Q1 projection input)
__device__ float   g_Qn[ELEMS];                // LN(Q) fp32, tf32-pre-rounded
__device__ bf16    g_Kh[ELEMS];                // LN(K), compacted per batch
__device__ bf16    g_Wqh[Dc*Dc], g_Wkh[Dc*Dc], g_Wvh[Dc*Dc];
__device__ float   g_Wot[Dc*Dc];               // Wo, tf32-pre-rounded fp32
__device__ uint8_t g_Q1f8[ELEMS], g_K1f8[ELEMS];  // Q/K projections (e4m3, x16 scale)
__device__ bf16    g_V1b[ELEMS];               // V projection (bf16)
__device__ bf16    g_O1[ELEMS];                // attention output (bf16)
__device__ float   g_O2[ELEMS];                // Q + relu(Qn @ Wo^T + bo)
__device__ int     g_pos[NTOK];
__device__ int     g_cmask[NTOK];
__device__ int     g_cnt[Bc];

// ---------------- PTX helpers ---------------------------------------------------
__device__ __forceinline__ uint32_t smem_u32(const void* p) {
    uint32_t a;
    asm("{ .reg .u64 t; cvta.to.shared.u64 t, %1; cvt.u32.u64 %0, t; }" : "=r"(a) : "l"(p));
    return a;
}
__device__ __forceinline__ void cpa16(uint32_t saddr, const void* g) {
    asm volatile("cp.async.cg.shared.global [%0], [%1], 16;" :: "r"(saddr), "l"(g) : "memory");
}
__device__ __forceinline__ void cp_commit() {
    asm volatile("cp.async.commit_group;" ::: "memory");
}
template<int N> __device__ __forceinline__ void cp_wait() {
    asm volatile("cp.async.wait_group %0;" :: "n"(N) : "memory");
}
__device__ __forceinline__ void ldm4(uint32_t* r, uint32_t a) {
    asm volatile("ldmatrix.sync.aligned.m8n8.x4.shared.b16 {%0,%1,%2,%3}, [%4];"
        : "=r"(r[0]), "=r"(r[1]), "=r"(r[2]), "=r"(r[3]) : "r"(a));
}
__device__ __forceinline__ void ldm4t(uint32_t* r, uint32_t a) {
    asm volatile("ldmatrix.sync.aligned.m8n8.x4.trans.shared.b16 {%0,%1,%2,%3}, [%4];"
        : "=r"(r[0]), "=r"(r[1]), "=r"(r[2]), "=r"(r[3]) : "r"(a));
}
__device__ __forceinline__ void mmabf(float* d, const uint32_t* a, const uint32_t* b) {
    asm volatile("mma.sync.aligned.m16n8k16.row.col.f32.bf16.bf16.f32 "
        "{%0,%1,%2,%3}, {%4,%5,%6,%7}, {%8,%9}, {%0,%1,%2,%3};"
        : "+f"(d[0]), "+f"(d[1]), "+f"(d[2]), "+f"(d[3])
        : "r"(a[0]), "r"(a[1]), "r"(a[2]), "r"(a[3]), "r"(b[0]), "r"(b[1]));
}
__device__ __forceinline__ void mmaf8(float* d, const uint32_t* a, const uint32_t* b) {
    asm volatile("mma.sync.aligned.m16n8k32.row.col.f32.e4m3.e4m3.f32 "
        "{%0,%1,%2,%3}, {%4,%5,%6,%7}, {%8,%9}, {%0,%1,%2,%3};"
        : "+f"(d[0]), "+f"(d[1]), "+f"(d[2]), "+f"(d[3])
        : "r"(a[0]), "r"(a[1]), "r"(a[2]), "r"(a[3]), "r"(b[0]), "r"(b[1]));
}
__device__ __forceinline__ void mmatf(float* d, const uint32_t* a, uint32_t b0, uint32_t b1) {
    asm volatile("mma.sync.aligned.m16n8k8.row.col.f32.tf32.tf32.f32 "
        "{%0,%1,%2,%3}, {%4,%5,%6,%7}, {%8,%9}, {%0,%1,%2,%3};"
        : "+f"(d[0]), "+f"(d[1]), "+f"(d[2]), "+f"(d[3])
        : "r"(a[0]), "r"(a[1]), "r"(a[2]), "r"(a[3]), "r"(b0), "r"(b1));
}
__device__ __forceinline__ float round_tf32(float f) {
    uint32_t y;
    asm("cvt.rna.tf32.f32 %0, %1;" : "=r"(y) : "f"(f));
    return __uint_as_float(y);
}
__device__ __forceinline__ uint32_t packbf2(float lo, float hi) {
    __nv_bfloat162 t = __floats2bfloat162_rn(lo, hi);
    return *(uint32_t*)&t;
}
__device__ __forceinline__ uint16_t packf8(float lo, float hi) {
    uint16_t r;
    asm("cvt.rn.satfinite.e4m3x2.f32 %0, %1, %2;" : "=h"(r) : "f"(hi), "f"(lo));
    return r;
}

// ---------------- mask prefix + compact-domain mask + pad zeroing ---------------
__global__ __launch_bounds__(1024) void prefix_kernel(const int* __restrict__ mask,
                                                      int* __restrict__ pos,
                                                      int* __restrict__ cmask,
                                                      int* __restrict__ cnt,
                                                      bf16* __restrict__ Knc) {
    int b = blockIdx.x;
    const int* m = mask + b * SKc;
    int t = threadIdx.x;
    int lane = t & 31, w = t >> 5;
    int v0 = m[2 * t], v1 = m[2 * t + 1];
    int s = v0 + v1;
    int sc = s;
    #pragma unroll
    for (int o = 1; o < 32; o <<= 1) {
        int n = __shfl_up_sync(0xffffffffu, sc, o);
        if (lane >= o) sc += n;
    }
    __shared__ int wt[32];
    if (lane == 31) wt[w] = sc;
    __syncthreads();
    if (w == 0) {
        int x = wt[lane];
        #pragma unroll
        for (int o = 1; o < 32; o <<= 1) {
            int n = __shfl_up_sync(0xffffffffu, x, o);
            if (lane >= o) x += n;
        }
        wt[lane] = x;
    }
    __syncthreads();
    int base = ((w > 0) ? wt[w - 1] : 0) + (sc - s);
    pos[b * SKc + 2 * t]     = base;
    pos[b * SKc + 2 * t + 1] = base + v0;
    int total = wt[31];
    if (t == 0) cnt[b] = total;
    cmask[b * SKc + 2 * t]     = (2 * t     < total) ? 1 : 0;
    cmask[b * SKc + 2 * t + 1] = (2 * t + 1 < total) ? 1 : 0;
    int padN = ((total + 127) >> 7) << 7;
    if (padN > SKc) padN = SKc;
    int nz = (padN - total) * (Dc / 4);
    uint2* dst = (uint2*)(Knc + ((size_t)b * SKc + total) * Dc);
    uint2 z; z.x = 0; z.y = 0;
    for (int i = t; i < nz; i += 1024) dst[i] = z;
}

// ---------------- merged LN (Q + compacted K) + weight conversion ----------------
__global__ __launch_bounds__(256) void ln_wconv_kernel(const float* __restrict__ Qx,
                                                       const float* __restrict__ Kx,
                                                       const float* __restrict__ gq,
                                                       const float* __restrict__ bq,
                                                       const float* __restrict__ gk,
                                                       const float* __restrict__ bk,
                                                       const int* __restrict__ mask,
                                                       const int* __restrict__ pos,
                                                       const float* __restrict__ Wq,
                                                       const float* __restrict__ Wk,
                                                       const float* __restrict__ Wv,
                                                       const float* __restrict__ Wo,
                                                       bf16* __restrict__ Qhi,
                                                       float* __restrict__ Qf32,
                                                       bf16* __restrict__ Khi,
                                                       bf16* __restrict__ qh,
                                                       bf16* __restrict__ kh,
                                                       bf16* __restrict__ vh,
                                                       float* __restrict__ ot) {
    int blk = blockIdx.x;
    if (blk >= 2 * NTOK) {
        int wb = blk - 2 * NTOK;
        int m = wb >> 10;
        int i = (wb & 1023) * 256 + threadIdx.x;
        size_t base = (size_t)i * 4;
        if (m == 3) {
            float4 v = ((const float4*)Wo)[i];
            float4 r;
            r.x = round_tf32(v.x); r.y = round_tf32(v.y);
            r.z = round_tf32(v.z); r.w = round_tf32(v.w);
            *(float4*)(ot + base) = r;
            return;
        }
        const float* W = (m == 0) ? Wq : (m == 1) ? Wk : Wv;
        bf16* hi = (m == 0) ? qh : (m == 1) ? kh : vh;
        float4 v = ((const float4*)W)[i];
        __nv_bfloat162 hA = __floats2bfloat162_rn(v.x, v.y);
        __nv_bfloat162 hB = __floats2bfloat162_rn(v.z, v.w);
        *(__nv_bfloat162*)(hi + base)     = hA;
        *(__nv_bfloat162*)(hi + base + 2) = hB;
        return;
    }
    int isK = (blk >= NTOK);
    int row = isK ? (blk - NTOK) : blk;
    if (isK && !mask[row]) return;
    const float* x = isK ? Kx : Qx;
    const float* g = isK ? gk : gq;
    const float* b = isK ? bk : bq;
    int t = threadIdx.x;
    const float4* xr = (const float4*)(x + (size_t)row * Dc);
    float4 v = xr[t];
    float s  = v.x + v.y + v.z + v.w;
    float ss = v.x*v.x + v.y*v.y + v.z*v.z + v.w*v.w;
    #pragma unroll
    for (int o = 16; o > 0; o >>= 1) {
        s  += __shfl_xor_sync(0xffffffffu, s,  o);
        ss += __shfl_xor_sync(0xffffffffu, ss, o);
    }
    __shared__ float red[2][8];
    int w = t >> 5, l = t & 31;
    if (l == 0) { red[0][w] = s; red[1][w] = ss; }
    __syncthreads();
    float st = 0.f, sst = 0.f;
    #pragma unroll
    for (int i = 0; i < 8; i++) { st += red[0][i]; sst += red[1][i]; }
    float mean = st * (1.0f / Dc);
    float var  = sst * (1.0f / Dc) - mean * mean;
    float rstd = rsqrtf(var + 1e-5f);
    float4 gg = ((const float4*)g)[t];
    float4 bb = ((const float4*)b)[t];
    float4 o;
    o.x = (v.x - mean) * rstd * gg.x + bb.x;
    o.y = (v.y - mean) * rstd * gg.y + bb.y;
    o.z = (v.z - mean) * rstd * gg.z + bb.z;
    o.w = (v.w - mean) * rstd * gg.w + bb.w;
    __nv_bfloat162 hA = __floats2bfloat162_rn(o.x, o.y);
    __nv_bfloat162 hB = __floats2bfloat162_rn(o.z, o.w);
    if (!isK) {
        size_t base = (size_t)row * Dc + t * 4;
        float4 r;
        r.x = round_tf32(o.x); r.y = round_tf32(o.y);
        r.z = round_tf32(o.z); r.w = round_tf32(o.w);
        *(float4*)(Qf32 + base) = r;
        *(__nv_bfloat162*)(Qhi + base)     = hA;
        *(__nv_bfloat162*)(Qhi + base + 2) = hB;
    } else {
        int bb_ = row >> 11;
        size_t base = ((size_t)bb_ * SKc + pos[row]) * Dc + t * 4;
        *(__nv_bfloat162*)(Khi + base)     = hA;
        *(__nv_bfloat162*)(Khi + base + 2) = hB;
    }
}

// ---------------- projections GEMM (z=1..3; 3-stage, 1 barrier/chunk) ------------
#define STG   36864
#define GSMEM (3*STG)
__global__ __launch_bounds__(256, 2) void gemm_proj_kernel(const bf16* __restrict__ Qh,
                                                           const bf16* __restrict__ Kh,
                                                           const bf16* __restrict__ Wqh,
                                                           const bf16* __restrict__ Wkh,
                                                           const bf16* __restrict__ Wvh,
                                                           const float* __restrict__ bq,
                                                           const float* __restrict__ bk,
                                                           const float* __restrict__ bv,
                                                           const int* __restrict__ cnt,
                                                           uint8_t* __restrict__ Q1f8,
                                                           uint8_t* __restrict__ K1f8,
                                                           bf16* __restrict__ V1b) {
    int z = blockIdx.z + 1;
    int m0 = blockIdx.y * 128, n0 = blockIdx.x * 128;
    if (z >= 2) {
        int batch = m0 >> 11;
        int ml = m0 & 2047;
        int padN = ((cnt[batch] + 127) >> 7) << 7;
        if (ml >= padN) return;
    }
    extern __shared__ char sm[];
    uint32_t sb = smem_u32(sm);
    int tid = threadIdx.x, lane = tid & 31, warp = tid >> 5;
    int wm = (warp >> 1) * 32, wn = (warp & 1) * 64;
    int cq = 2 * (lane & 3);

    float acc[2][8][4];
    #pragma unroll
    for (int mt = 0; mt < 2; mt++)
        #pragma unroll
        for (int nt = 0; nt < 8; nt++)
            #pragma unroll
            for (int j = 0; j < 4; j++) acc[mt][nt][j] = 0.f;

    const bf16* A  = (z == 1) ? Qh : Kh;
    const bf16* Wh = (z == 1) ? Wqh : (z == 2) ? Wkh : Wvh;
    const float* bias = (z == 1) ? bq : (z == 2) ? bk : bv;
    const bf16* Ahg = A  + (size_t)m0 * Dc;
    const bf16* Whg = Wh + (size_t)n0 * Dc;

    auto ldstage = [&](int st, int k0) {
        uint32_t s0 = sb + st * STG;
        #pragma unroll
        for (int i = 0; i < 4; i++) {
            int idx = tid + i * 256;
            int r = idx >> 3, c = idx & 7;
            uint32_t so = r * 144 + c * 16;
            size_t   go = (size_t)r * Dc + k0 + c * 8;
            cpa16(s0 +         so, Ahg + go);
            cpa16(s0 + 18432 + so, Whg + go);
        }
    };
    ldstage(0, 0);  cp_commit();
    ldstage(1, 64); cp_commit();

    int g8 = lane >> 3, r8 = lane & 7;
    uint32_t aoffl = (lane & 15) * 144 + (lane >> 4) * 16;
    uint32_t boffl = ((g8 >> 1) * 8 + r8) * 144 + (g8 & 1) * 16;
    int st = 0, ld = 2;

    #pragma unroll 1
    for (int c = 0; c < 16; c++) {
        if (c + 1 < 16) cp_wait<1>(); else cp_wait<0>();
        __syncthreads();
        if (c + 2 < 16) { ldstage(ld, (c + 2) * 64); cp_commit(); }
        uint32_t SA = sb + st * STG;
        #pragma unroll
        for (int ks = 0; ks < 4; ks++) {
            uint32_t ah[2][4];
            #pragma unroll
            for (int mt = 0; mt < 2; mt++)
                ldm4(ah[mt], SA + (wm + mt * 16) * 144 + aoffl + ks * 32);
            #pragma unroll
            for (int np = 0; np < 4; np++) {
                uint32_t bh[4];
                ldm4(bh, SA + 18432 + (wn + np * 16) * 144 + boffl + ks * 32);
                #pragma unroll
                for (int mt = 0; mt < 2; mt++) {
                    mmabf(acc[mt][2*np],   ah[mt], bh);
                    mmabf(acc[mt][2*np+1], ah[mt], bh + 2);
                }
            }
        }
        st = (st == 2) ? 0 : st + 1;
        ld = (ld == 2) ? 0 : ld + 1;
    }

    #pragma unroll
    for (int mt = 0; mt < 2; mt++) {
        int row0 = m0 + wm + mt * 16 + (lane >> 2);
        #pragma unroll
        for (int nt = 0; nt < 8; nt++) {
            int col = n0 + wn + nt * 8 + cq;
            float b0 = bias[col], b1 = bias[col + 1];
            float c00 = acc[mt][nt][0] + b0, c01 = acc[mt][nt][1] + b1;
            float c10 = acc[mt][nt][2] + b0, c11 = acc[mt][nt][3] + b1;
            if (z == 3) {
                *(uint32_t*)(V1b + (size_t)row0 * Dc + col)       = packbf2(c00, c01);
                *(uint32_t*)(V1b + (size_t)(row0 + 8) * Dc + col) = packbf2(c10, c11);
            } else {
                uint8_t* dst = (z == 1) ? Q1f8 : K1f8;
                *(uint16_t*)(dst + (size_t)row0 * Dc + col)       = packf8(c00 * 16.f, c01 * 16.f);
                *(uint16_t*)(dst + (size_t)(row0 + 8) * Dc + col) = packf8(c10 * 16.f, c11 * 16.f);
            }
        }
    }
}

// ---------------- fused Wo-tf32 GEMM + flash attention (one launch) -------------
// blocks [0,256): Wo tile (m = bid>>3, n = bid&7), 3-stage tf32 pipeline
// blocks [256,768): attention (idx=bid-256: qtile = idx&15, h = (idx>>4)&15, b = idx>>8)
#define AQ_OFF   0
#define AK_OFF   10240
#define AV_OFF   25600
#define AM_OFF   53248
__global__ __launch_bounds__(256, 2) void wo_attn_kernel(const float* __restrict__ Qn,
                                                         const float* __restrict__ Wot,
                                                         const float* __restrict__ bo,
                                                         const float* __restrict__ Qres,
                                                         float* __restrict__ O2,
                                                         const uint8_t* __restrict__ Qf8,
                                                         const uint8_t* __restrict__ Kf8,
                                                         const bf16* __restrict__ Vb,
                                                         const int* __restrict__ cmask,
                                                         const int* __restrict__ cnt,
                                                         bf16* __restrict__ O1) {
    extern __shared__ char sm[];
    uint32_t sb = smem_u32(sm);
    int tid = threadIdx.x, lane = tid & 31, warp = tid >> 5;

    if (blockIdx.x < 256) {
        // ================= Wo tf32 GEMM tile =================
        int m0 = (blockIdx.x >> 3) * 128, n0 = (blockIdx.x & 7) * 128;
        int wm = (warp >> 1) * 32, wn = (warp & 1) * 64;
        int cq = 2 * (lane & 3);
        float acc[2][8][4];
        #pragma unroll
        for (int mt = 0; mt < 2; mt++)
            #pragma unroll
            for (int nt = 0; nt < 8; nt++)
                #pragma unroll
                for (int j = 0; j < 4; j++) acc[mt][nt][j] = 0.f;

        const float* Ag = Qn  + (size_t)m0 * Dc;
        const float* Wg = Wot + (size_t)n0 * Dc;
        auto ldstage = [&](int st, int k0) {
            uint32_t s0 = sb + st * STG;
            #pragma unroll
            for (int i = 0; i < 4; i++) {
                int idx = tid + i * 256;
                int r = idx >> 3, c = idx & 7;
                uint32_t so = r * 144 + c * 16;
                size_t   go = (size_t)r * Dc + k0 + c * 4;
                cpa16(s0 +         so, Ag + go);
                cpa16(s0 + 18432 + so, Wg + go);
            }
        };
        ldstage(0, 0);  cp_commit();
        ldstage(1, 32); cp_commit();
        uint32_t aoffl = (lane & 15) * 144 + (lane >> 4) * 16;
        uint32_t boffl = ((lane & 7) + ((lane >> 4) << 3)) * 144 + ((lane >> 3) & 1) * 16;
        int st = 0, ld = 2;
        #pragma unroll 1
        for (int c = 0; c < 32; c++) {
            if (c + 1 < 32) cp_wait<1>(); else cp_wait<0>();
            __syncthreads();
            if (c + 2 < 32) { ldstage(ld, (c + 2) * 32); cp_commit(); }
            uint32_t SA = sb + st * STG;
            #pragma unroll
            for (int ks = 0; ks < 4; ks++) {
                uint32_t ar[2][4];
                #pragma unroll
                for (int mt = 0; mt < 2; mt++)
                    ldm4(ar[mt], SA + (wm + mt * 16) * 144 + aoffl + ks * 32);
                #pragma unroll
                for (int np = 0; np < 4; np++) {
                    uint32_t br[4];
                    ldm4(br, SA + 18432 + (wn + np * 16) * 144 + boffl + ks * 32);
                    #pragma unroll
                    for (int mt = 0; mt < 2; mt++) {
                        mmatf(acc[mt][2*np],   ar[mt], br[0], br[1]);
                        mmatf(acc[mt][2*np+1], ar[mt], br[2], br[3]);
                    }
                }
            }
            st = (st == 2) ? 0 : st + 1;
            ld = (ld == 2) ? 0 : ld + 1;
        }
        #pragma unroll
        for (int mt = 0; mt < 2; mt++) {
            int row0 = m0 + wm + mt * 16 + (lane >> 2);
            #pragma unroll
            for (int nt = 0; nt < 8; nt++) {
                int col = n0 + wn + nt * 8 + cq;
                float b0 = bo[col], b1 = bo[col + 1];
                float2 q0 = *(const float2*)(Qres + (size_t)row0 * Dc + col);
                float2 q1 = *(const float2*)(Qres + (size_t)(row0 + 8) * Dc + col);
                float2 v0 = make_float2(q0.x + fmaxf(acc[mt][nt][0] + b0, 0.f),
                                        q0.y + fmaxf(acc[mt][nt][1] + b1, 0.f));
                float2 v1 = make_float2(q1.x + fmaxf(acc[mt][nt][2] + b0, 0.f),
                                        q1.y + fmaxf(acc[mt][nt][3] + b1, 0.f));
                *(float2*)(O2 + (size_t)row0 * Dc + col)       = v0;
                *(float2*)(O2 + (size_t)(row0 + 8) * Dc + col) = v1;
            }
        }
        return;
    }

    // ================= attention tile =================
    int idx = blockIdx.x - 256;
    int q0 = (idx & 15) * 128;
    int h  = (idx >> 4) & 15;
    int b  = idx >> 8;
    const uint8_t* Qg = Qf8 + ((size_t)(b * SQc + q0)) * Dc + h * DHc;
    const uint8_t* Kg = Kf8 + ((size_t)b * SKc) * Dc + h * DHc;
    const bf16*    Vg = Vb  + ((size_t)b * SKc) * Dc + h * DHc;
    const int*     mg = cmask + b * SKc;
    int nch = (cnt[b] + 63) >> 6;

    auto ldkv = [&](int st, int k0) {
        {
            int r = tid >> 2, c = tid & 3;
            cpa16(sb + AK_OFF + st * 5120 + r * 80 + c * 16,
                  Kg + (size_t)(k0 + r) * Dc + c * 16);
        }
        #pragma unroll
        for (int i = 0; i < 2; i++) {
            int idx2 = tid + i * 256;
            int r = idx2 >> 3, c = idx2 & 7;
            cpa16(sb + AV_OFF + st * 9216 + r * 144 + c * 16,
                  Vg + (size_t)(k0 + r) * Dc + c * 8);
        }
        if (tid < 16) cpa16(sb + AM_OFF + st * 256 + tid * 16, mg + k0 + tid * 4);
    };

    #pragma unroll
    for (int i = 0; i < 2; i++) {
        int idx2 = tid + i * 256;
        int r = idx2 >> 2, c = idx2 & 3;
        cpa16(sb + AQ_OFF + r * 80 + c * 16, Qg + (size_t)r * Dc + c * 16);
    }
    ldkv(0, 0);
    cp_commit();
    if (nch > 1) { ldkv(1, 64); cp_commit(); }

    int m0 = warp * 16;
    int g8 = lane >> 3, r8 = lane & 7;
    int cq = 2 * (lane & 3);
    uint32_t qaddr = sb + AQ_OFF + (m0 + (lane & 15)) * 80 + (lane >> 4) * 16;
    uint32_t klane = ((g8 >> 1) * 8 + r8) * 80 + (g8 & 1) * 16;
    uint32_t vlane = ((g8 & 1) * 8 + r8) * 144 + (g8 >> 1) * 16;
    const float SC2 = 0.03125f / 256.f;

    float o[8][4];
    #pragma unroll
    for (int dt = 0; dt < 8; dt++)
        #pragma unroll
        for (int j = 0; j < 4; j++) o[dt][j] = 0.f;
    float ls0 = 0.f, ls1 = 0.f;
    int st = 0, ld = 2;

    #pragma unroll 1
    for (int c = 0; c < nch; c++) {
        if (c + 1 < nch) cp_wait<1>(); else cp_wait<0>();
        __syncthreads();
        if (c + 2 < nch) { ldkv(ld, (c + 2) * 64); cp_commit(); }

        uint32_t Kst = sb + AK_OFF + st * 5120 + klane;
        uint32_t Vst = sb + AV_OFF + st * 9216 + vlane;
        const int* mp = (const int*)(sm + AM_OFF + st * 256);

        float s_[8][4];
        #pragma unroll
        for (int nt = 0; nt < 8; nt++)
            #pragma unroll
            for (int j = 0; j < 4; j++) s_[nt][j] = 0.f;
        #pragma unroll
        for (int ks = 0; ks < 2; ks++) {
            uint32_t aq[4];
            ldm4(aq, qaddr + ks * 32);
            #pragma unroll
            for (int np = 0; np < 4; np++) {
                uint32_t bk[4];
                ldm4(bk, Kst + np * 1280 + ks * 32);
                mmaf8(s_[2*np],   aq, bk);
                mmaf8(s_[2*np+1], aq, bk + 2);
            }
        }

        uint32_t pr0[8], pr1[8];
        #pragma unroll
        for (int nt = 0; nt < 8; nt++) {
            float f0 = (float)mp[nt * 8 + cq];
            float f1 = (float)mp[nt * 8 + cq + 1];
            float p0 = __expf(s_[nt][0] * SC2) * f0;
            float p1 = __expf(s_[nt][1] * SC2) * f1;
            float p2 = __expf(s_[nt][2] * SC2) * f0;
            float p3 = __expf(s_[nt][3] * SC2) * f1;
            ls0 += p0 + p1;
            ls1 += p2 + p3;
            pr0[nt] = packbf2(p0, p1);
            pr1[nt] = packbf2(p2, p3);
        }

        #pragma unroll
        for (int ks2 = 0; ks2 < 4; ks2++) {
            uint32_t pf[4] = { pr0[2*ks2], pr1[2*ks2], pr0[2*ks2+1], pr1[2*ks2+1] };
            #pragma unroll
            for (int dp = 0; dp < 4; dp++) {
                uint32_t bv[4];
                ldm4t(bv, Vst + ks2 * 2304 + dp * 32);
                mmabf(o[2*dp],   pf, bv);
                mmabf(o[2*dp+1], pf, bv + 2);
            }
        }
        st = (st == 2) ? 0 : st + 1;
        ld = (ld == 2) ? 0 : ld + 1;
    }

    ls0 += __shfl_xor_sync(0xffffffffu, ls0, 1);
    ls0 += __shfl_xor_sync(0xffffffffu, ls0, 2);
    ls1 += __shfl_xor_sync(0xffffffffu, ls1, 1);
    ls1 += __shfl_xor_sync(0xffffffffu, ls1, 2);
    float i0 = 1.f / ls0, i1 = 1.f / ls1;
    int row0 = q0 + m0 + (lane >> 2);
    bf16* Or0 = O1 + ((size_t)(b * SQc) + row0) * Dc + h * DHc + cq;
    bf16* Or1 = Or0 + (size_t)8 * Dc;
    #pragma unroll
    for (int dt = 0; dt < 8; dt++) {
        *(uint32_t*)(Or0 + dt * 8) = packbf2(o[dt][0] * i0, o[dt][1] * i0);
        *(uint32_t*)(Or1 + dt * 8) = packbf2(o[dt][2] * i1, o[dt][3] * i1);
    }
}

// ---------------- final LayerNorm over (bf16 O1 + O2s) --------------------------
__global__ __launch_bounds__(256) void final_ln_kernel(const bf16* __restrict__ O1,
                                                       const float* __restrict__ O2s,
                                                       const float* __restrict__ g,
                                                       const float* __restrict__ b,
                                                       float* __restrict__ out) {
    int row = blockIdx.x;
    int t = threadIdx.x;
    size_t base = (size_t)row * Dc;
    __nv_bfloat162 a0 = *(const __nv_bfloat162*)(O1 + base + t * 4);
    __nv_bfloat162 a1 = *(const __nv_bfloat162*)(O1 + base + t * 4 + 2);
    float4 o2 = ((const float4*)(O2s + base))[t];
    float4 v;
    v.x = __bfloat162float(a0.x) + o2.x;
    v.y = __bfloat162float(a0.y) + o2.y;
    v.z = __bfloat162float(a1.x) + o2.z;
    v.w = __bfloat162float(a1.y) + o2.w;
    float s  = v.x + v.y + v.z + v.w;
    float ss = v.x*v.x + v.y*v.y + v.z*v.z + v.w*v.w;
    #pragma unroll
    for (int o = 16; o > 0; o >>= 1) {
        s  += __shfl_xor_sync(0xffffffffu, s,  o);
        ss += __shfl_xor_sync(0xffffffffu, ss, o);
    }
    __shared__ float red[2][8];
    int w = t >> 5, l = t & 31;
    if (l == 0) { red[0][w] = s; red[1][w] = ss; }
    __syncthreads();
    float st = 0.f, sst = 0.f;
    #pragma unroll
    for (int i = 0; i < 8; i++) { st += red[0][i]; sst += red[1][i]; }
    float mean = st * (1.0f / Dc);
    float var  = sst * (1.0f / Dc) - mean * mean;
    float rstd = rsqrtf(var + 1e-5f);
    float4 gg = ((const float4*)g)[t];
    float4 bb = ((const float4*)b)[t];
    float4 o;
    o.x = (v.x - mean) * rstd * gg.x + bb.x;
    o.y = (v.y - mean) * rstd * gg.y + bb.y;
    o.z = (v.z - mean) * rstd * gg.z + bb.z;
    o.w = (v.w - mean) * rstd * gg.w + bb.w;
    ((float4*)(out + base))[t] = o;
}

// ---------------- launch -------------------------------------------------------
extern "C" void kernel_launch(void* const* d_in, const int* in_sizes, int n_in,
                              void* d_out, int out_size) {
    const float* Q       = (const float*)d_in[0];
    const float* K       = (const float*)d_in[1];
    const int*   padm    = (const int*)d_in[2];
    const float* Wq      = (const float*)d_in[3];
    const float* Wk      = (const float*)d_in[4];
    const float* Wv      = (const float*)d_in[5];
    const float* Wo      = (const float*)d_in[6];
    const float* bq      = (const float*)d_in[7];
    const float* bk      = (const float*)d_in[8];
    const float* bv      = (const float*)d_in[9];
    const float* bo      = (const float*)d_in[10];
    const float* ln_q_g  = (const float*)d_in[11];
    const float* ln_q_b  = (const float*)d_in[12];
    const float* ln_kv_g = (const float*)d_in[13];
    const float* ln_kv_b = (const float*)d_in[14];
    const float* ln_f_g  = (const float*)d_in[15];
    const float* ln_f_b  = (const float*)d_in[16];
    float* out = (float*)d_out;

    bf16 *pQh, *pKh, *pWqh, *pWkh, *pWvh, *pV1b, *pO1;
    uint8_t *pQ1f8, *pK1f8;
    float *pQn, *pWot, *pO2;
    int *pPos, *pCmask, *pCnt;
    cudaGetSymbolAddress((void**)&pQh, g_Qh);
    cudaGetSymbolAddress((void**)&pQn, g_Qn);
    cudaGetSymbolAddress((void**)&pKh, g_Kh);
    cudaGetSymbolAddress((void**)&pWqh, g_Wqh);
    cudaGetSymbolAddress((void**)&pWkh, g_Wkh);
    cudaGetSymbolAddress((void**)&pWvh, g_Wvh);
    cudaGetSymbolAddress((void**)&pWot, g_Wot);
    cudaGetSymbolAddress((void**)&pQ1f8, g_Q1f8);
    cudaGetSymbolAddress((void**)&pK1f8, g_K1f8);
    cudaGetSymbolAddress((void**)&pV1b, g_V1b);
    cudaGetSymbolAddress((void**)&pO1, g_O1);
    cudaGetSymbolAddress((void**)&pO2, g_O2);
    cudaGetSymbolAddress((void**)&pPos, g_pos);
    cudaGetSymbolAddress((void**)&pCmask, g_cmask);
    cudaGetSymbolAddress((void**)&pCnt, g_cnt);

    cudaFuncSetAttribute(gemm_proj_kernel, cudaFuncAttributeMaxDynamicSharedMemorySize, GSMEM);
    cudaFuncSetAttribute(wo_attn_kernel,   cudaFuncAttributeMaxDynamicSharedMemorySize, GSMEM);

    prefix_kernel<<<Bc, 1024>>>(padm, pPos, pCmask, pCnt, pKh);
    ln_wconv_kernel<<<2 * NTOK + 4096, 256>>>(Q, K, ln_q_g, ln_q_b, ln_kv_g, ln_kv_b,
                                              padm, pPos, Wq, Wk, Wv, Wo,
                                              pQh, pQn, pKh, pWqh, pWkh, pWvh, pWot);

    dim3 gproj(Dc / 128, NTOK / 128, 3);   // (8, 32, 3)
    gemm_proj_kernel<<<gproj, 256, GSMEM>>>(pQh, pKh, pWqh, pWkh, pWvh,
                                            bq, bk, bv, pCnt, pQ1f8, pK1f8, pV1b);

    // fused: 256 Wo-GEMM CTAs + 512 attention CTAs in ONE launch
    wo_attn_kernel<<<768, 256, GSMEM>>>(pQn, pWot, bo, Q, pO2,
                                        pQ1f8, pK1f8, pV1b, pCmask, pCnt, pO1);

    final_ln_kernel<<<NTOK, 256>>>(pO1, pO2, ln_f_g, ln_f_b, out);
}

// round 17
// speedup vs baseline: 1.1287x; 1.0307x over previous
#include <cuda_runtime.h>
#include <cuda_bf16.h>
#include <cstdint>
#include <math.h>

#define Bc  2
#define SQc 2048
#define SKc 2048
#define Dc  1024
#define Hc  16
#define DHc 64
#define NTOK (Bc*SQc)
#define ELEMS (Bc*SQc*Dc)

typedef __nv_bfloat16 bf16;

// ---------------- scratch (static device arrays; no allocation) ----------------
__device__ bf16    g_Qh[ELEMS];                // LN(Q) bf16 (Q1 projection input)
__device__ float   g_Qn[ELEMS];                // LN(Q) fp32, tf32-pre-rounded
__device__ bf16    g_Kh[ELEMS];                // LN(K), compacted per batch
__device__ bf16    g_Wqh[Dc*Dc], g_Wkh[Dc*Dc], g_Wvh[Dc*Dc];
__device__ float   g_Wot[Dc*Dc];               // Wo, tf32-pre-rounded fp32
__device__ uint8_t g_Q1f8[ELEMS], g_K1f8[ELEMS];  // Q/K projections (e4m3, x16 scale)
__device__ bf16    g_V1b[ELEMS];               // V projection (bf16)
__device__ bf16    g_O1[ELEMS];                // attention output (bf16)
__device__ float   g_O2[ELEMS];                // Q + relu(Qn @ Wo^T + bo)
__device__ int     g_pos[NTOK];
__device__ int     g_cnt[Bc];

// ---------------- PTX helpers ---------------------------------------------------
__device__ __forceinline__ uint32_t smem_u32(const void* p) {
    uint32_t a;
    asm("{ .reg .u64 t; cvta.to.shared.u64 t, %1; cvt.u32.u64 %0, t; }" : "=r"(a) : "l"(p));
    return a;
}
__device__ __forceinline__ void cpa16(uint32_t saddr, const void* g) {
    asm volatile("cp.async.cg.shared.global [%0], [%1], 16;" :: "r"(saddr), "l"(g) : "memory");
}
__device__ __forceinline__ void cp_commit() {
    asm volatile("cp.async.commit_group;" ::: "memory");
}
template<int N> __device__ __forceinline__ void cp_wait() {
    asm volatile("cp.async.wait_group %0;" :: "n"(N) : "memory");
}
__device__ __forceinline__ void ldm4(uint32_t* r, uint32_t a) {
    asm volatile("ldmatrix.sync.aligned.m8n8.x4.shared.b16 {%0,%1,%2,%3}, [%4];"
        : "=r"(r[0]), "=r"(r[1]), "=r"(r[2]), "=r"(r[3]) : "r"(a));
}
__device__ __forceinline__ void ldm4t(uint32_t* r, uint32_t a) {
    asm volatile("ldmatrix.sync.aligned.m8n8.x4.trans.shared.b16 {%0,%1,%2,%3}, [%4];"
        : "=r"(r[0]), "=r"(r[1]), "=r"(r[2]), "=r"(r[3]) : "r"(a));
}
__device__ __forceinline__ void mmabf(float* d, const uint32_t* a, const uint32_t* b) {
    asm volatile("mma.sync.aligned.m16n8k16.row.col.f32.bf16.bf16.f32 "
        "{%0,%1,%2,%3}, {%4,%5,%6,%7}, {%8,%9}, {%0,%1,%2,%3};"
        : "+f"(d[0]), "+f"(d[1]), "+f"(d[2]), "+f"(d[3])
        : "r"(a[0]), "r"(a[1]), "r"(a[2]), "r"(a[3]), "r"(b[0]), "r"(b[1]));
}
__device__ __forceinline__ void mmaf8(float* d, const uint32_t* a, const uint32_t* b) {
    asm volatile("mma.sync.aligned.m16n8k32.row.col.f32.e4m3.e4m3.f32 "
        "{%0,%1,%2,%3}, {%4,%5,%6,%7}, {%8,%9}, {%0,%1,%2,%3};"
        : "+f"(d[0]), "+f"(d[1]), "+f"(d[2]), "+f"(d[3])
        : "r"(a[0]), "r"(a[1]), "r"(a[2]), "r"(a[3]), "r"(b[0]), "r"(b[1]));
}
__device__ __forceinline__ void mmatf(float* d, const uint32_t* a, uint32_t b0, uint32_t b1) {
    asm volatile("mma.sync.aligned.m16n8k8.row.col.f32.tf32.tf32.f32 "
        "{%0,%1,%2,%3}, {%4,%5,%6,%7}, {%8,%9}, {%0,%1,%2,%3};"
        : "+f"(d[0]), "+f"(d[1]), "+f"(d[2]), "+f"(d[3])
        : "r"(a[0]), "r"(a[1]), "r"(a[2]), "r"(a[3]), "r"(b0), "r"(b1));
}
__device__ __forceinline__ float round_tf32(float f) {
    uint32_t y;
    asm("cvt.rna.tf32.f32 %0, %1;" : "=r"(y) : "f"(f));
    return __uint_as_float(y);
}
__device__ __forceinline__ float ex2f(float x) {
    float y;
    asm("ex2.approx.f32 %0, %1;" : "=f"(y) : "f"(x));
    return y;
}
__device__ __forceinline__ uint32_t packbf2(float lo, float hi) {
    __nv_bfloat162 t = __floats2bfloat162_rn(lo, hi);
    return *(uint32_t*)&t;
}
__device__ __forceinline__ uint16_t packf8(float lo, float hi) {
    uint16_t r;
    asm("cvt.rn.satfinite.e4m3x2.f32 %0, %1, %2;" : "=h"(r) : "f"(hi), "f"(lo));
    return r;
}

// ---------------- mask prefix + pad zeroing -------------------------------------
__global__ __launch_bounds__(1024) void prefix_kernel(const int* __restrict__ mask,
                                                      int* __restrict__ pos,
                                                      int* __restrict__ cnt,
                                                      bf16* __restrict__ Knc) {
    int b = blockIdx.x;
    const int* m = mask + b * SKc;
    int t = threadIdx.x;
    int lane = t & 31, w = t >> 5;
    int v0 = m[2 * t], v1 = m[2 * t + 1];
    int s = v0 + v1;
    int sc = s;
    #pragma unroll
    for (int o = 1; o < 32; o <<= 1) {
        int n = __shfl_up_sync(0xffffffffu, sc, o);
        if (lane >= o) sc += n;
    }
    __shared__ int wt[32];
    if (lane == 31) wt[w] = sc;
    __syncthreads();
    if (w == 0) {
        int x = wt[lane];
        #pragma unroll
        for (int o = 1; o < 32; o <<= 1) {
            int n = __shfl_up_sync(0xffffffffu, x, o);
            if (lane >= o) x += n;
        }
        wt[lane] = x;
    }
    __syncthreads();
    int base = ((w > 0) ? wt[w - 1] : 0) + (sc - s);
    pos[b * SKc + 2 * t]     = base;
    pos[b * SKc + 2 * t + 1] = base + v0;
    int total = wt[31];
    if (t == 0) cnt[b] = total;
    int padN = ((total + 127) >> 7) << 7;
    if (padN > SKc) padN = SKc;
    int nz = (padN - total) * (Dc / 4);
    uint2* dst = (uint2*)(Knc + ((size_t)b * SKc + total) * Dc);
    uint2 z; z.x = 0; z.y = 0;
    for (int i = t; i < nz; i += 1024) dst[i] = z;
}

// ---------------- merged LN (Q + compacted K) + weight conversion ----------------
__global__ __launch_bounds__(256) void ln_wconv_kernel(const float* __restrict__ Qx,
                                                       const float* __restrict__ Kx,
                                                       const float* __restrict__ gq,
                                                       const float* __restrict__ bq,
                                                       const float* __restrict__ gk,
                                                       const float* __restrict__ bk,
                                                       const int* __restrict__ mask,
                                                       const int* __restrict__ pos,
                                                       const float* __restrict__ Wq,
                                                       const float* __restrict__ Wk,
                                                       const float* __restrict__ Wv,
                                                       const float* __restrict__ Wo,
                                                       bf16* __restrict__ Qhi,
                                                       float* __restrict__ Qf32,
                                                       bf16* __restrict__ Khi,
                                                       bf16* __restrict__ qh,
                                                       bf16* __restrict__ kh,
                                                       bf16* __restrict__ vh,
                                                       float* __restrict__ ot) {
    int blk = blockIdx.x;
    if (blk >= 2 * NTOK) {
        int wb = blk - 2 * NTOK;
        int m = wb >> 10;
        int i = (wb & 1023) * 256 + threadIdx.x;
        size_t base = (size_t)i * 4;
        if (m == 3) {
            float4 v = ((const float4*)Wo)[i];
            float4 r;
            r.x = round_tf32(v.x); r.y = round_tf32(v.y);
            r.z = round_tf32(v.z); r.w = round_tf32(v.w);
            *(float4*)(ot + base) = r;
            return;
        }
        const float* W = (m == 0) ? Wq : (m == 1) ? Wk : Wv;
        bf16* hi = (m == 0) ? qh : (m == 1) ? kh : vh;
        float4 v = ((const float4*)W)[i];
        __nv_bfloat162 hA = __floats2bfloat162_rn(v.x, v.y);
        __nv_bfloat162 hB = __floats2bfloat162_rn(v.z, v.w);
        *(__nv_bfloat162*)(hi + base)     = hA;
        *(__nv_bfloat162*)(hi + base + 2) = hB;
        return;
    }
    int isK = (blk >= NTOK);
    int row = isK ? (blk - NTOK) : blk;
    if (isK && !mask[row]) return;
    const float* x = isK ? Kx : Qx;
    const float* g = isK ? gk : gq;
    const float* b = isK ? bk : bq;
    int t = threadIdx.x;
    const float4* xr = (const float4*)(x + (size_t)row * Dc);
    float4 v = xr[t];
    float s  = v.x + v.y + v.z + v.w;
    float ss = v.x*v.x + v.y*v.y + v.z*v.z + v.w*v.w;
    #pragma unroll
    for (int o = 16; o > 0; o >>= 1) {
        s  += __shfl_xor_sync(0xffffffffu, s,  o);
        ss += __shfl_xor_sync(0xffffffffu, ss, o);
    }
    __shared__ float red[2][8];
    int w = t >> 5, l = t & 31;
    if (l == 0) { red[0][w] = s; red[1][w] = ss; }
    __syncthreads();
    float st = 0.f, sst = 0.f;
    #pragma unroll
    for (int i = 0; i < 8; i++) { st += red[0][i]; sst += red[1][i]; }
    float mean = st * (1.0f / Dc);
    float var  = sst * (1.0f / Dc) - mean * mean;
    float rstd = rsqrtf(var + 1e-5f);
    float4 gg = ((const float4*)g)[t];
    float4 bb = ((const float4*)b)[t];
    float4 o;
    o.x = (v.x - mean) * rstd * gg.x + bb.x;
    o.y = (v.y - mean) * rstd * gg.y + bb.y;
    o.z = (v.z - mean) * rstd * gg.z + bb.z;
    o.w = (v.w - mean) * rstd * gg.w + bb.w;
    __nv_bfloat162 hA = __floats2bfloat162_rn(o.x, o.y);
    __nv_bfloat162 hB = __floats2bfloat162_rn(o.z, o.w);
    if (!isK) {
        size_t base = (size_t)row * Dc + t * 4;
        float4 r;
        r.x = round_tf32(o.x); r.y = round_tf32(o.y);
        r.z = round_tf32(o.z); r.w = round_tf32(o.w);
        *(float4*)(Qf32 + base) = r;
        *(__nv_bfloat162*)(Qhi + base)     = hA;
        *(__nv_bfloat162*)(Qhi + base + 2) = hB;
    } else {
        int bb_ = row >> 11;
        size_t base = ((size_t)bb_ * SKc + pos[row]) * Dc + t * 4;
        *(__nv_bfloat162*)(Khi + base)     = hA;
        *(__nv_bfloat162*)(Khi + base + 2) = hB;
    }
}

// ---------------- projections GEMM (z=1..3; 3-stage, 1 barrier/chunk) ------------
#define STG   36864
#define GSMEM (3*STG)
__global__ __launch_bounds__(256, 2) void gemm_proj_kernel(const bf16* __restrict__ Qh,
                                                           const bf16* __restrict__ Kh,
                                                           const bf16* __restrict__ Wqh,
                                                           const bf16* __restrict__ Wkh,
                                                           const bf16* __restrict__ Wvh,
                                                           const float* __restrict__ bq,
                                                           const float* __restrict__ bk,
                                                           const float* __restrict__ bv,
                                                           const int* __restrict__ cnt,
                                                           uint8_t* __restrict__ Q1f8,
                                                           uint8_t* __restrict__ K1f8,
                                                           bf16* __restrict__ V1b) {
    int z = blockIdx.z + 1;
    int m0 = blockIdx.y * 128, n0 = blockIdx.x * 128;
    if (z >= 2) {
        int batch = m0 >> 11;
        int ml = m0 & 2047;
        int padN = ((cnt[batch] + 127) >> 7) << 7;
        if (ml >= padN) return;
    }
    extern __shared__ char sm[];
    uint32_t sb = smem_u32(sm);
    int tid = threadIdx.x, lane = tid & 31, warp = tid >> 5;
    int wm = (warp >> 1) * 32, wn = (warp & 1) * 64;
    int cq = 2 * (lane & 3);

    float acc[2][8][4];
    #pragma unroll
    for (int mt = 0; mt < 2; mt++)
        #pragma unroll
        for (int nt = 0; nt < 8; nt++)
            #pragma unroll
            for (int j = 0; j < 4; j++) acc[mt][nt][j] = 0.f;

    const bf16* A  = (z == 1) ? Qh : Kh;
    const bf16* Wh = (z == 1) ? Wqh : (z == 2) ? Wkh : Wvh;
    const float* bias = (z == 1) ? bq : (z == 2) ? bk : bv;
    const bf16* Ahg = A  + (size_t)m0 * Dc;
    const bf16* Whg = Wh + (size_t)n0 * Dc;

    auto ldstage = [&](int st, int k0) {
        uint32_t s0 = sb + st * STG;
        #pragma unroll
        for (int i = 0; i < 4; i++) {
            int idx = tid + i * 256;
            int r = idx >> 3, c = idx & 7;
            uint32_t so = r * 144 + c * 16;
            size_t   go = (size_t)r * Dc + k0 + c * 8;
            cpa16(s0 +         so, Ahg + go);
            cpa16(s0 + 18432 + so, Whg + go);
        }
    };
    ldstage(0, 0);  cp_commit();
    ldstage(1, 64); cp_commit();

    int g8 = lane >> 3, r8 = lane & 7;
    uint32_t aoffl = (lane & 15) * 144 + (lane >> 4) * 16;
    uint32_t boffl = ((g8 >> 1) * 8 + r8) * 144 + (g8 & 1) * 16;
    int st = 0, ld = 2;

    #pragma unroll 1
    for (int c = 0; c < 16; c++) {
        if (c + 1 < 16) cp_wait<1>(); else cp_wait<0>();
        __syncthreads();
        if (c + 2 < 16) { ldstage(ld, (c + 2) * 64); cp_commit(); }
        uint32_t SA = sb + st * STG;
        #pragma unroll
        for (int ks = 0; ks < 4; ks++) {
            uint32_t ah[2][4];
            #pragma unroll
            for (int mt = 0; mt < 2; mt++)
                ldm4(ah[mt], SA + (wm + mt * 16) * 144 + aoffl + ks * 32);
            #pragma unroll
            for (int np = 0; np < 4; np++) {
                uint32_t bh[4];
                ldm4(bh, SA + 18432 + (wn + np * 16) * 144 + boffl + ks * 32);
                #pragma unroll
                for (int mt = 0; mt < 2; mt++) {
                    mmabf(acc[mt][2*np],   ah[mt], bh);
                    mmabf(acc[mt][2*np+1], ah[mt], bh + 2);
                }
            }
        }
        st = (st == 2) ? 0 : st + 1;
        ld = (ld == 2) ? 0 : ld + 1;
    }

    #pragma unroll
    for (int mt = 0; mt < 2; mt++) {
        int row0 = m0 + wm + mt * 16 + (lane >> 2);
        #pragma unroll
        for (int nt = 0; nt < 8; nt++) {
            int col = n0 + wn + nt * 8 + cq;
            float b0 = bias[col], b1 = bias[col + 1];
            float c00 = acc[mt][nt][0] + b0, c01 = acc[mt][nt][1] + b1;
            float c10 = acc[mt][nt][2] + b0, c11 = acc[mt][nt][3] + b1;
            if (z == 3) {
                *(uint32_t*)(V1b + (size_t)row0 * Dc + col)       = packbf2(c00, c01);
                *(uint32_t*)(V1b + (size_t)(row0 + 8) * Dc + col) = packbf2(c10, c11);
            } else {
                uint8_t* dst = (z == 1) ? Q1f8 : K1f8;
                *(uint16_t*)(dst + (size_t)row0 * Dc + col)       = packf8(c00 * 16.f, c01 * 16.f);
                *(uint16_t*)(dst + (size_t)(row0 + 8) * Dc + col) = packf8(c10 * 16.f, c11 * 16.f);
            }
        }
    }
}

// ---------------- fused Wo-tf32 GEMM + flash attention (one launch) -------------
// blocks [0,256): Wo tile; blocks [256,768): attention (maskless; pad-corrected ls)
#define AQ_OFF   0
#define AK_OFF   10240
#define AV_OFF   25600
__global__ __launch_bounds__(256, 2) void wo_attn_kernel(const float* __restrict__ Qn,
                                                         const float* __restrict__ Wot,
                                                         const float* __restrict__ bo,
                                                         const float* __restrict__ Qres,
                                                         float* __restrict__ O2,
                                                         const uint8_t* __restrict__ Qf8,
                                                         const uint8_t* __restrict__ Kf8,
                                                         const bf16* __restrict__ Vb,
                                                         const int* __restrict__ cnt,
                                                         bf16* __restrict__ O1) {
    extern __shared__ char sm[];
    uint32_t sb = smem_u32(sm);
    int tid = threadIdx.x, lane = tid & 31, warp = tid >> 5;

    if (blockIdx.x < 256) {
        // ================= Wo tf32 GEMM tile =================
        int m0 = (blockIdx.x >> 3) * 128, n0 = (blockIdx.x & 7) * 128;
        int wm = (warp >> 1) * 32, wn = (warp & 1) * 64;
        int cq = 2 * (lane & 3);
        float acc[2][8][4];
        #pragma unroll
        for (int mt = 0; mt < 2; mt++)
            #pragma unroll
            for (int nt = 0; nt < 8; nt++)
                #pragma unroll
                for (int j = 0; j < 4; j++) acc[mt][nt][j] = 0.f;

        const float* Ag = Qn  + (size_t)m0 * Dc;
        const float* Wg = Wot + (size_t)n0 * Dc;
        auto ldstage = [&](int st, int k0) {
            uint32_t s0 = sb + st * STG;
            #pragma unroll
            for (int i = 0; i < 4; i++) {
                int idx = tid + i * 256;
                int r = idx >> 3, c = idx & 7;
                uint32_t so = r * 144 + c * 16;
                size_t   go = (size_t)r * Dc + k0 + c * 4;
                cpa16(s0 +         so, Ag + go);
                cpa16(s0 + 18432 + so, Wg + go);
            }
        };
        ldstage(0, 0);  cp_commit();
        ldstage(1, 32); cp_commit();
        uint32_t aoffl = (lane & 15) * 144 + (lane >> 4) * 16;
        uint32_t boffl = ((lane & 7) + ((lane >> 4) << 3)) * 144 + ((lane >> 3) & 1) * 16;
        int st = 0, ld = 2;
        #pragma unroll 1
        for (int c = 0; c < 32; c++) {
            if (c + 1 < 32) cp_wait<1>(); else cp_wait<0>();
            __syncthreads();
            if (c + 2 < 32) { ldstage(ld, (c + 2) * 32); cp_commit(); }
            uint32_t SA = sb + st * STG;
            #pragma unroll
            for (int ks = 0; ks < 4; ks++) {
                uint32_t ar[2][4];
                #pragma unroll
                for (int mt = 0; mt < 2; mt++)
                    ldm4(ar[mt], SA + (wm + mt * 16) * 144 + aoffl + ks * 32);
                #pragma unroll
                for (int np = 0; np < 4; np++) {
                    uint32_t br[4];
                    ldm4(br, SA + 18432 + (wn + np * 16) * 144 + boffl + ks * 32);
                    #pragma unroll
                    for (int mt = 0; mt < 2; mt++) {
                        mmatf(acc[mt][2*np],   ar[mt], br[0], br[1]);
                        mmatf(acc[mt][2*np+1], ar[mt], br[2], br[3]);
                    }
                }
            }
            st = (st == 2) ? 0 : st + 1;
            ld = (ld == 2) ? 0 : ld + 1;
        }
        #pragma unroll
        for (int mt = 0; mt < 2; mt++) {
            int row0 = m0 + wm + mt * 16 + (lane >> 2);
            #pragma unroll
            for (int nt = 0; nt < 8; nt++) {
                int col = n0 + wn + nt * 8 + cq;
                float b0 = bo[col], b1 = bo[col + 1];
                float2 q0 = *(const float2*)(Qres + (size_t)row0 * Dc + col);
                float2 q1 = *(const float2*)(Qres + (size_t)(row0 + 8) * Dc + col);
                float2 v0 = make_float2(q0.x + fmaxf(acc[mt][nt][0] + b0, 0.f),
                                        q0.y + fmaxf(acc[mt][nt][1] + b1, 0.f));
                float2 v1 = make_float2(q1.x + fmaxf(acc[mt][nt][2] + b0, 0.f),
                                        q1.y + fmaxf(acc[mt][nt][3] + b1, 0.f));
                *(float2*)(O2 + (size_t)row0 * Dc + col)       = v0;
                *(float2*)(O2 + (size_t)(row0 + 8) * Dc + col) = v1;
            }
        }
        return;
    }

    // ================= attention tile (maskless) =================
    int idx = blockIdx.x - 256;
    int q0 = (idx & 15) * 128;
    int h  = (idx >> 4) & 15;
    int b  = idx >> 8;
    const uint8_t* Qg = Qf8 + ((size_t)(b * SQc + q0)) * Dc + h * DHc;
    const uint8_t* Kg = Kf8 + ((size_t)b * SKc) * Dc + h * DHc;
    const bf16*    Vg = Vb  + ((size_t)b * SKc) * Dc + h * DHc;
    int cb = cnt[b];
    int nch = (cb + 63) >> 6;
    float padcorr = (float)(nch * 64 - cb);   // pads contribute exactly 1.0 each to ls

    auto ldkv = [&](int st, int k0) {
        {
            int r = tid >> 2, c = tid & 3;
            cpa16(sb + AK_OFF + st * 5120 + r * 80 + c * 16,
                  Kg + (size_t)(k0 + r) * Dc + c * 16);
        }
        #pragma unroll
        for (int i = 0; i < 2; i++) {
            int idx2 = tid + i * 256;
            int r = idx2 >> 3, c = idx2 & 7;
            cpa16(sb + AV_OFF + st * 9216 + r * 144 + c * 16,
                  Vg + (size_t)(k0 + r) * Dc + c * 8);
        }
    };

    #pragma unroll
    for (int i = 0; i < 2; i++) {
        int idx2 = tid + i * 256;
        int r = idx2 >> 2, c = idx2 & 3;
        cpa16(sb + AQ_OFF + r * 80 + c * 16, Qg + (size_t)r * Dc + c * 16);
    }
    ldkv(0, 0);
    cp_commit();
    if (nch > 1) { ldkv(1, 64); cp_commit(); }

    int m0 = warp * 16;
    int g8 = lane >> 3, r8 = lane & 7;
    int cq = 2 * (lane & 3);
    uint32_t qaddr = sb + AQ_OFF + (m0 + (lane & 15)) * 80 + (lane >> 4) * 16;
    uint32_t klane = ((g8 >> 1) * 8 + r8) * 80 + (g8 & 1) * 16;
    uint32_t vlane = ((g8 & 1) * 8 + r8) * 144 + (g8 >> 1) * 16;
    const float SC2L = (0.03125f / 256.f) * 1.44269504f;  // fold log2e into scale

    float o[8][4];
    #pragma unroll
    for (int dt = 0; dt < 8; dt++)
        #pragma unroll
        for (int j = 0; j < 4; j++) o[dt][j] = 0.f;
    float ls0 = 0.f, ls1 = 0.f;
    int st = 0, ld = 2;

    #pragma unroll 1
    for (int c = 0; c < nch; c++) {
        if (c + 1 < nch) cp_wait<1>(); else cp_wait<0>();
        __syncthreads();
        if (c + 2 < nch) { ldkv(ld, (c + 2) * 64); cp_commit(); }

        uint32_t Kst = sb + AK_OFF + st * 5120 + klane;
        uint32_t Vst = sb + AV_OFF + st * 9216 + vlane;

        float s_[8][4];
        #pragma unroll
        for (int nt = 0; nt < 8; nt++)
            #pragma unroll
            for (int j = 0; j < 4; j++) s_[nt][j] = 0.f;
        #pragma unroll
        for (int ks = 0; ks < 2; ks++) {
            uint32_t aq[4];
            ldm4(aq, qaddr + ks * 32);
            #pragma unroll
            for (int np = 0; np < 4; np++) {
                uint32_t bk[4];
                ldm4(bk, Kst + np * 1280 + ks * 32);
                mmaf8(s_[2*np],   aq, bk);
                mmaf8(s_[2*np+1], aq, bk + 2);
            }
        }

        uint32_t pr0[8], pr1[8];
        #pragma unroll
        for (int nt = 0; nt < 8; nt++) {
            float p0 = ex2f(s_[nt][0] * SC2L);
            float p1 = ex2f(s_[nt][1] * SC2L);
            float p2 = ex2f(s_[nt][2] * SC2L);
            float p3 = ex2f(s_[nt][3] * SC2L);
            ls0 += p0 + p1;
            ls1 += p2 + p3;
            pr0[nt] = packbf2(p0, p1);
            pr1[nt] = packbf2(p2, p3);
        }

        #pragma unroll
        for (int ks2 = 0; ks2 < 4; ks2++) {
            uint32_t pf[4] = { pr0[2*ks2], pr1[2*ks2], pr0[2*ks2+1], pr1[2*ks2+1] };
            #pragma unroll
            for (int dp = 0; dp < 4; dp++) {
                uint32_t bv[4];
                ldm4t(bv, Vst + ks2 * 2304 + dp * 32);
                mmabf(o[2*dp],   pf, bv);
                mmabf(o[2*dp+1], pf, bv + 2);
            }
        }
        st = (st == 2) ? 0 : st + 1;
        ld = (ld == 2) ? 0 : ld + 1;
    }

    ls0 += __shfl_xor_sync(0xffffffffu, ls0, 1);
    ls0 += __shfl_xor_sync(0xffffffffu, ls0, 2);
    ls1 += __shfl_xor_sync(0xffffffffu, ls1, 1);
    ls1 += __shfl_xor_sync(0xffffffffu, ls1, 2);
    float i0 = 1.f / (ls0 - padcorr);
    float i1 = 1.f / (ls1 - padcorr);
    int row0 = q0 + m0 + (lane >> 2);
    bf16* Or0 = O1 + ((size_t)(b * SQc) + row0) * Dc + h * DHc + cq;
    bf16* Or1 = Or0 + (size_t)8 * Dc;
    #pragma unroll
    for (int dt = 0; dt < 8; dt++) {
        *(uint32_t*)(Or0 + dt * 8) = packbf2(o[dt][0] * i0, o[dt][1] * i0);
        *(uint32_t*)(Or1 + dt * 8) = packbf2(o[dt][2] * i1, o[dt][3] * i1);
    }
}

// ---------------- final LayerNorm over (bf16 O1 + O2s) --------------------------
__global__ __launch_bounds__(256) void final_ln_kernel(const bf16* __restrict__ O1,
                                                       const float* __restrict__ O2s,
                                                       const float* __restrict__ g,
                                                       const float* __restrict__ b,
                                                       float* __restrict__ out) {
    int row = blockIdx.x;
    int t = threadIdx.x;
    size_t base = (size_t)row * Dc;
    __nv_bfloat162 a0 = *(const __nv_bfloat162*)(O1 + base + t * 4);
    __nv_bfloat162 a1 = *(const __nv_bfloat162*)(O1 + base + t * 4 + 2);
    float4 o2 = ((const float4*)(O2s + base))[t];
    float4 v;
    v.x = __bfloat162float(a0.x) + o2.x;
    v.y = __bfloat162float(a0.y) + o2.y;
    v.z = __bfloat162float(a1.x) + o2.z;
    v.w = __bfloat162float(a1.y) + o2.w;
    float s  = v.x + v.y + v.z + v.w;
    float ss = v.x*v.x + v.y*v.y + v.z*v.z + v.w*v.w;
    #pragma unroll
    for (int o = 16; o > 0; o >>= 1) {
        s  += __shfl_xor_sync(0xffffffffu, s,  o);
        ss += __shfl_xor_sync(0xffffffffu, ss, o);
    }
    __shared__ float red[2][8];
    int w = t >> 5, l = t & 31;
    if (l == 0) { red[0][w] = s; red[1][w] = ss; }
    __syncthreads();
    float st = 0.f, sst = 0.f;
    #pragma unroll
    for (int i = 0; i < 8; i++) { st += red[0][i]; sst += red[1][i]; }
    float mean = st * (1.0f / Dc);
    float var  = sst * (1.0f / Dc) - mean * mean;
    float rstd = rsqrtf(var + 1e-5f);
    float4 gg = ((const float4*)g)[t];
    float4 bb = ((const float4*)b)[t];
    float4 o;
    o.x = (v.x - mean) * rstd * gg.x + bb.x;
    o.y = (v.y - mean) * rstd * gg.y + bb.y;
    o.z = (v.z - mean) * rstd * gg.z + bb.z;
    o.w = (v.w - mean) * rstd * gg.w + bb.w;
    ((float4*)(out + base))[t] = o;
}

// ---------------- launch -------------------------------------------------------
extern "C" void kernel_launch(void* const* d_in, const int* in_sizes, int n_in,
                              void* d_out, int out_size) {
    const float* Q       = (const float*)d_in[0];
    const float* K       = (const float*)d_in[1];
    const int*   padm    = (const int*)d_in[2];
    const float* Wq      = (const float*)d_in[3];
    const float* Wk      = (const float*)d_in[4];
    const float* Wv      = (const float*)d_in[5];
    const float* Wo      = (const float*)d_in[6];
    const float* bq      = (const float*)d_in[7];
    const float* bk      = (const float*)d_in[8];
    const float* bv      = (const float*)d_in[9];
    const float* bo      = (const float*)d_in[10];
    const float* ln_q_g  = (const float*)d_in[11];
    const float* ln_q_b  = (const float*)d_in[12];
    const float* ln_kv_g = (const float*)d_in[13];
    const float* ln_kv_b = (const float*)d_in[14];
    const float* ln_f_g  = (const float*)d_in[15];
    const float* ln_f_b  = (const float*)d_in[16];
    float* out = (float*)d_out;

    bf16 *pQh, *pKh, *pWqh, *pWkh, *pWvh, *pV1b, *pO1;
    uint8_t *pQ1f8, *pK1f8;
    float *pQn, *pWot, *pO2;
    int *pPos, *pCnt;
    cudaGetSymbolAddress((void**)&pQh, g_Qh);
    cudaGetSymbolAddress((void**)&pQn, g_Qn);
    cudaGetSymbolAddress((void**)&pKh, g_Kh);
    cudaGetSymbolAddress((void**)&pWqh, g_Wqh);
    cudaGetSymbolAddress((void**)&pWkh, g_Wkh);
    cudaGetSymbolAddress((void**)&pWvh, g_Wvh);
    cudaGetSymbolAddress((void**)&pWot, g_Wot);
    cudaGetSymbolAddress((void**)&pQ1f8, g_Q1f8);
    cudaGetSymbolAddress((void**)&pK1f8, g_K1f8);
    cudaGetSymbolAddress((void**)&pV1b, g_V1b);
    cudaGetSymbolAddress((void**)&pO1, g_O1);
    cudaGetSymbolAddress((void**)&pO2, g_O2);
    cudaGetSymbolAddress((void**)&pPos, g_pos);
    cudaGetSymbolAddress((void**)&pCnt, g_cnt);

    cudaFuncSetAttribute(gemm_proj_kernel, cudaFuncAttributeMaxDynamicSharedMemorySize, GSMEM);
    cudaFuncSetAttribute(wo_attn_kernel,   cudaFuncAttributeMaxDynamicSharedMemorySize, GSMEM);

    prefix_kernel<<<Bc, 1024>>>(padm, pPos, pCnt, pKh);
    ln_wconv_kernel<<<2 * NTOK + 4096, 256>>>(Q, K, ln_q_g, ln_q_b, ln_kv_g, ln_kv_b,
                                              padm, pPos, Wq, Wk, Wv, Wo,
                                              pQh, pQn, pKh, pWqh, pWkh, pWvh, pWot);

    dim3 gproj(Dc / 128, NTOK / 128, 3);   // (8, 32, 3)
    gemm_proj_kernel<<<gproj, 256, GSMEM>>>(pQh, pKh, pWqh, pWkh, pWvh,
                                            bq, bk, bv, pCnt, pQ1f8, pK1f8, pV1b);

    // fused: 256 Wo-GEMM CTAs + 512 attention CTAs in ONE launch
    wo_attn_kernel<<<768, 256, GSMEM>>>(pQn, pWot, bo, Q, pO2,
                                        pQ1f8, pK1f8, pV1b, pCnt, pO1);

    final_ln_kernel<<<NTOK, 256>>>(pO1, pO2, ln_f_g, ln_f_b, out);
}